// round 3
// baseline (speedup 1.0000x reference)
#include <cuda_runtime.h>
#include <cuda_bf16.h>

// Problem constants (static per reference)
constexpr int B  = 2;
constexpr int S  = 6;
constexpr int N  = 10000;
constexpr int C  = 128;
constexpr int D  = 4;
constexpr int NH = 4;     // heads
constexpr int NP = 8;     // points
constexpr int Hf = 32;
constexpr int Wf = 88;
constexpr int M  = Hf * Wf;   // 2816
constexpr int MASK_ELEMS = S * B * N * D;  // 480000

// Scratch (device globals; no allocation allowed)
__device__ float g_vproj [S * B * M * C];        // (s,b,m,c) c = head*32+lane
__device__ float g_off   [B * N * NH * NP * 2];  // raw offsets (pixel units)
__device__ float g_logits[B * N * NH * NP];      // attn logits (pre softmax)
__device__ float g_slots [B * N * C];            // masked-mean slots pre W_out
__device__ int   g_mask_stride;                  // bytes per bev_mask element

// ---------------------------------------------------------------------------
// Kernel 0: detect bev_mask element width. Values are 0/1 in any storage
// dtype; classify by which byte positions (mod 8) ever hold a nonzero byte:
//   uint8 bools  -> positions 1 and 5 occur      -> stride 1
//   f32 (0/1.0)  -> positions {2,3,6,7}          -> stride 4
//   int32        -> positions {0,4}              -> stride 4
//   int64/f64    -> otherwise                    -> stride 8
// ---------------------------------------------------------------------------
__global__ void k_detect(const unsigned char* __restrict__ mask)
{
    __shared__ unsigned occ_s;
    if (threadIdx.x == 0) occ_s = 0u;
    __syncthreads();
    unsigned occ = 0u;
    for (int i = threadIdx.x; i < MASK_ELEMS; i += blockDim.x)  // first 480000 bytes: safe for any stride
        if (mask[i]) occ |= 1u << (i & 7);
    #pragma unroll
    for (int o = 16; o > 0; o >>= 1) occ |= __shfl_xor_sync(0xffffffffu, occ, o);
    if ((threadIdx.x & 31) == 0) atomicOr(&occ_s, occ);
    __syncthreads();
    if (threadIdx.x == 0) {
        unsigned o = occ_s;
        int st;
        if      (o & 0x22u) st = 1;   // pos 1 or 5 -> byte bools
        else if (o & 0x1Cu) st = 4;   // pos 2,3,4 -> 4-byte elements
        else                st = 8;   // 8-byte elements
        g_mask_stride = st;
    }
}

__device__ __forceinline__ int mask_nz(const unsigned char* __restrict__ mask,
                                       long long elem, int st)
{
    const unsigned char* p = mask + elem * st;
    int v = 0;
    for (int j = 0; j < st; j++) v |= p[j];
    return v != 0;
}

// ---------------------------------------------------------------------------
// Kernel 1: value projection  v = value @ W_value + b_value
// 8 rows per block, 128 threads (thread = out channel).
// ---------------------------------------------------------------------------
__global__ void __launch_bounds__(128) k_vproj(
    const float* __restrict__ value,  // (S,M,B,C)
    const float* __restrict__ Wv,     // (C,C)
    const float* __restrict__ bv)     // (C,)
{
    __shared__ float sv[8][C];
    const int t   = threadIdx.x;
    const int ro0 = blockIdx.x * 8;   // output row index: (s*B+b)*M + m

    {
        int i = t >> 4;               // row 0..7
        int c4 = (t & 15) * 4;
        #pragma unroll
        for (int half = 0; half < 2; half++) {
            int ro = ro0 + i;
            int sb = ro / M, m = ro % M;
            int s  = sb / B, b = sb % B;
            const float4 v4 = *(const float4*)(value + ((size_t)((s * M + m) * B + b) * C + c4 + half * 64));
            *(float4*)&sv[i][c4 + half * 64] = v4;
        }
    }
    __syncthreads();

    float acc[8];
    const float bias = __ldg(bv + t);
    #pragma unroll
    for (int r = 0; r < 8; r++) acc[r] = bias;

    #pragma unroll 4
    for (int k = 0; k < C; k++) {
        float w = __ldg(Wv + k * C + t);
        #pragma unroll
        for (int r = 0; r < 8; r++) acc[r] = fmaf(sv[r][k], w, acc[r]);
    }
    #pragma unroll
    for (int r = 0; r < 8; r++) g_vproj[(size_t)(ro0 + r) * C + t] = acc[r];
}

// ---------------------------------------------------------------------------
// Kernel 2: q = query + query_pos ; offsets = q@W_off + b_off ; logits = q@W_a + b_a
// Once per (b,n) — q does not depend on camera s.
// ---------------------------------------------------------------------------
__global__ void __launch_bounds__(128) k_qproj(
    const float* __restrict__ query,  // (B,N,C)
    const float* __restrict__ qpos,   // (B,N,C)
    const float* __restrict__ Woff,   // (C,64)
    const float* __restrict__ boff,   // (64,)
    const float* __restrict__ Wa,     // (C,32)
    const float* __restrict__ ba)     // (32,)
{
    __shared__ float sq[8][C];
    const int t   = threadIdx.x;
    const int ro0 = blockIdx.x * 8;   // row = b*N + n

    #pragma unroll
    for (int i = 0; i < 8; i++) {
        int off = (ro0 + i) * C + t;
        sq[i][t] = query[off] + qpos[off];
    }
    __syncthreads();

    if (t < 96) {
        const float* Wp;
        int stride;
        float bias;
        if (t < 64) { Wp = Woff + t;        stride = 64; bias = __ldg(boff + t); }
        else        { Wp = Wa + (t - 64);   stride = 32; bias = __ldg(ba + t - 64); }

        float acc[8];
        #pragma unroll
        for (int r = 0; r < 8; r++) acc[r] = bias;

        #pragma unroll 4
        for (int k = 0; k < C; k++) {
            float w = __ldg(Wp + k * stride);
            #pragma unroll
            for (int r = 0; r < 8; r++) acc[r] = fmaf(sq[r][k], w, acc[r]);
        }
        #pragma unroll
        for (int r = 0; r < 8; r++) {
            int row = ro0 + r;
            if (t < 64) g_off[row * 64 + t]           = acc[r];
            else        g_logits[row * 32 + (t - 64)] = acc[r];
        }
    }
}

// ---------------------------------------------------------------------------
// Kernel 3: bilinear deformable sampling, fused across cameras + masked mean.
// 1 block per (b,n), 4 warps (one per head), lane = channel within head.
// ---------------------------------------------------------------------------
__device__ __forceinline__ float fetchv(const float* __restrict__ vb, int yi, int xi) {
    bool valid = ((unsigned)yi < (unsigned)Hf) && ((unsigned)xi < (unsigned)Wf);
    int yc = min(max(yi, 0), Hf - 1);
    int xc = min(max(xi, 0), Wf - 1);
    float v = __ldg(vb + (yc * Wf + xc) * C);
    return valid ? v : 0.0f;
}

__global__ void __launch_bounds__(128) k_sample(
    const float* __restrict__ refpts,           // (S,B,N,D,2)
    const unsigned char* __restrict__ bev_mask) // (S,B,N,D), stride detected
{
    const int row  = blockIdx.x;     // b*N + n
    const int b    = row / N;
    const int n    = row % N;
    const int t    = threadIdx.x;
    const int head = t >> 5;
    const int lane = t & 31;

    __shared__ float off_s[NH * NP * 2];
    __shared__ float aw_s[NH * NP];
    __shared__ int   sel_s[S];
    __shared__ int   hit_s[S];

    if (t < 64) off_s[t] = g_off[row * 64 + t];

    if (t >= 64 && t < 96) {         // warp 2: softmax over 8 points per head
        int j = t - 64;              // head*8 + p
        float l = g_logits[row * 32 + j];
        float m = l;
        #pragma unroll
        for (int o = 4; o > 0; o >>= 1)
            m = fmaxf(m, __shfl_xor_sync(0xffffffffu, m, o, 8));
        float e = expf(l - m);
        float ssum = e;
        #pragma unroll
        for (int o = 4; o > 0; o >>= 1)
            ssum += __shfl_xor_sync(0xffffffffu, ssum, o, 8);
        aw_s[j] = e / ssum;
    }

    if (t >= 96 && t < 96 + S) {     // warp 3: masks (stride-agnostic reads)
        int s = t - 96;
        int st = g_mask_stride;
        long long e0 = ((long long)(s * B + 0) * N + n) * D;
        long long eb = ((long long)(s * B + b) * N + n) * D;
        int sv = 0, hv = 0;
        #pragma unroll
        for (int d = 0; d < D; d++) {
            sv |= mask_nz(bev_mask, e0 + d, st);
            hv |= mask_nz(bev_mask, eb + d, st);
        }
        sel_s[s] = sv;
        hit_s[s] = hv;
    }
    __syncthreads();

    float cnt = 0.0f;
    #pragma unroll
    for (int s = 0; s < S; s++) cnt += (float)hit_s[s];
    cnt = fmaxf(cnt, 1.0f);

    // Per-point constants (offsets enter in raw pixel units)
    float ox[NP], oy[NP], wp[NP];
    #pragma unroll
    for (int p = 0; p < NP; p++) {
        ox[p] = off_s[(head * NP + p) * 2 + 0] - 0.5f;
        oy[p] = off_s[(head * NP + p) * 2 + 1] - 0.5f;
        wp[p] = aw_s[head * NP + p];
    }

    float acc = 0.0f;
    #pragma unroll
    for (int s = 0; s < S; s++) {
        if (!sel_s[s]) continue;     // batch-0 mask gates contribution (ref quirk)
        const float* vb = g_vproj + (size_t)((s * B + b) * M) * C + head * 32 + lane;
        const float* rp = refpts + (((size_t)(s * B + b) * N + n) * D) * 2;

        float rx[D], ry[D];
        #pragma unroll
        for (int dz = 0; dz < D; dz++) { rx[dz] = __ldg(rp + dz * 2); ry[dz] = __ldg(rp + dz * 2 + 1); }

        #pragma unroll
        for (int p = 0; p < NP; p++) {
            int dz = p & 3;          // p -> dz = p % D (reshape order)
            float x = fmaf(rx[dz], (float)Wf, ox[p]);
            float y = fmaf(ry[dz], (float)Hf, oy[p]);
            float xf = floorf(x), yf = floorf(y);
            float wx1 = x - xf, wy1 = y - yf;
            int x0 = (int)xf, y0 = (int)yf;

            float f00 = fetchv(vb, y0,     x0);
            float f01 = fetchv(vb, y0,     x0 + 1);
            float f10 = fetchv(vb, y0 + 1, x0);
            float f11 = fetchv(vb, y0 + 1, x0 + 1);

            float wx0 = 1.0f - wx1, wy0 = 1.0f - wy1;
            float bil = wy0 * fmaf(wx1, f01, wx0 * f00)
                      + wy1 * fmaf(wx1, f11, wx0 * f10);
            acc = fmaf(wp[p], bil, acc);
        }
    }
    g_slots[row * C + t] = acc / cnt;
}

// ---------------------------------------------------------------------------
// Kernel 4: out = slots @ W_out + b_out + query
// ---------------------------------------------------------------------------
__global__ void __launch_bounds__(128) k_out(
    const float* __restrict__ query,  // (B,N,C)
    const float* __restrict__ Wo,     // (C,C)
    const float* __restrict__ bo,     // (C,)
    float* __restrict__ out)          // (B,N,C)
{
    __shared__ float sv[8][C];
    const int t   = threadIdx.x;
    const int ro0 = blockIdx.x * 8;

    #pragma unroll
    for (int i = 0; i < 8; i++) sv[i][t] = g_slots[(ro0 + i) * C + t];
    __syncthreads();

    float acc[8];
    const float bias = __ldg(bo + t);
    #pragma unroll
    for (int r = 0; r < 8; r++) acc[r] = bias;

    #pragma unroll 4
    for (int k = 0; k < C; k++) {
        float w = __ldg(Wo + k * C + t);
        #pragma unroll
        for (int r = 0; r < 8; r++) acc[r] = fmaf(sv[r][k], w, acc[r]);
    }
    #pragma unroll
    for (int r = 0; r < 8; r++) {
        int off = (ro0 + r) * C + t;
        out[off] = acc[r] + query[off];
    }
}

// ---------------------------------------------------------------------------
// Launch. Input order: query, key, value, query_pos, reference_points_cam,
// bev_mask, spatial_shapes, W_value, b_value, W_offsets, b_offsets,
// W_attn, b_attn, W_out, b_out.
// ---------------------------------------------------------------------------
extern "C" void kernel_launch(void* const* d_in, const int* in_sizes, int n_in,
                              void* d_out, int out_size)
{
    const float* query = (const float*)d_in[0];
    // d_in[1] = key: unused by the reference math
    const float* value = (const float*)d_in[2];
    const float* qpos  = (const float*)d_in[3];
    const float* refp  = (const float*)d_in[4];
    const unsigned char* mask = (const unsigned char*)d_in[5];
    // d_in[6] = spatial_shapes (static, hardcoded H=32, W=88)
    const float* Wv   = (const float*)d_in[7];
    const float* bv   = (const float*)d_in[8];
    const float* Woff = (const float*)d_in[9];
    const float* boff = (const float*)d_in[10];
    const float* Wa   = (const float*)d_in[11];
    const float* ba   = (const float*)d_in[12];
    const float* Wo   = (const float*)d_in[13];
    const float* bo   = (const float*)d_in[14];
    float* out = (float*)d_out;

    k_detect<<<1, 1024>>>(mask);
    k_vproj <<<(S * B * M) / 8, 128>>>(value, Wv, bv);
    k_qproj <<<(B * N) / 8,     128>>>(query, qpos, Woff, boff, Wa, ba);
    k_sample<<< B * N,          128>>>(refp, mask);
    k_out   <<<(B * N) / 8,     128>>>(query, Wo, bo, out);
}

// round 4
// speedup vs baseline: 1.7777x; 1.7777x over previous
#include <cuda_runtime.h>
#include <cuda_bf16.h>

// Problem constants (static per reference)
constexpr int B  = 2;
constexpr int S  = 6;
constexpr int N  = 10000;
constexpr int C  = 128;
constexpr int D  = 4;
constexpr int NH = 4;     // heads
constexpr int NP = 8;     // points
constexpr int Hf = 32;
constexpr int Wf = 88;
constexpr int M  = Hf * Wf;   // 2816
constexpr int MASK_ELEMS = S * B * N * D;  // 480000

// Scratch (device globals; no allocation allowed)
__device__ float    g_vproj [S * B * M * C];        // (s,b,m,c)
__device__ float    g_off   [B * N * NH * NP * 2];  // offsets (pixel units)
__device__ float    g_logits[B * N * NH * NP];      // attn logits
__device__ float    g_slots [B * N * C];            // masked-mean slots
__device__ unsigned g_mask_occ;                     // byte-position occupancy (OR-only: idempotent)

// ---------------------------------------------------------------------------
// Kernel 0: bev_mask dtype probe. OR together which byte positions (mod 8)
// ever hold a nonzero byte over the first MASK_ELEMS bytes (safe lower bound
// for any element width). uint8 bools light positions 1/5; f32(1.0f) lights
// 2,3,6,7; int32 lights 0,4; int64/f64 only 0 or 6,7.
// atomicOr accumulation is idempotent -> deterministic across graph replays.
// ---------------------------------------------------------------------------
__global__ void k_detect(const uint4* __restrict__ mask16)
{
    unsigned occ = 0u;
    const int nvec = MASK_ELEMS / 16;  // 30000
    for (int i = blockIdx.x * blockDim.x + threadIdx.x; i < nvec; i += gridDim.x * blockDim.x) {
        uint4 v = __ldg(mask16 + i);
        unsigned w[4] = {v.x, v.y, v.z, v.w};
        #pragma unroll
        for (int wi = 0; wi < 4; wi++) {
            int base = (wi * 4) & 7;
            #pragma unroll
            for (int k = 0; k < 4; k++)
                if ((w[wi] >> (k * 8)) & 0xFFu) occ |= 1u << ((base + k) & 7);
        }
    }
    #pragma unroll
    for (int o = 16; o > 0; o >>= 1) occ |= __shfl_xor_sync(0xffffffffu, occ, o);
    if ((threadIdx.x & 31) == 0 && occ) atomicOr(&g_mask_occ, occ);
}

__device__ __forceinline__ int mask_nz(const unsigned char* __restrict__ mask,
                                       long long elem, int st)
{
    const unsigned char* p = mask + elem * st;
    int v = 0;
    for (int j = 0; j < st; j++) v |= p[j];
    return v != 0;
}

// ---------------------------------------------------------------------------
// Kernel 1: value projection  v = value @ W_value + b_value
// 16 rows per block, 128 threads (thread = out channel).
// ---------------------------------------------------------------------------
__global__ void __launch_bounds__(128) k_vproj(
    const float* __restrict__ value,  // (S,M,B,C)
    const float* __restrict__ Wv,     // (C,C)
    const float* __restrict__ bv)     // (C,)
{
    __shared__ float sv[16][C];
    const int t   = threadIdx.x;
    const int ro0 = blockIdx.x * 16;  // output row index: (s*B+b)*M + m

    for (int idx = t; idx < 16 * 32; idx += 128) {
        int i  = idx >> 5;            // row 0..15
        int c4 = (idx & 31) * 4;
        int ro = ro0 + i;
        int sb = ro / M, m = ro % M;
        int s  = sb / B, b = sb % B;
        const float4 v4 = *(const float4*)(value + ((size_t)((s * M + m) * B + b) * C + c4));
        *(float4*)&sv[i][c4] = v4;
    }
    __syncthreads();

    float acc[16];
    const float bias = __ldg(bv + t);
    #pragma unroll
    for (int r = 0; r < 16; r++) acc[r] = bias;

    #pragma unroll 4
    for (int k = 0; k < C; k++) {
        float w = __ldg(Wv + k * C + t);
        #pragma unroll
        for (int r = 0; r < 16; r++) acc[r] = fmaf(sv[r][k], w, acc[r]);
    }
    #pragma unroll
    for (int r = 0; r < 16; r++) g_vproj[(size_t)(ro0 + r) * C + t] = acc[r];
}

// ---------------------------------------------------------------------------
// Kernel 2: q = query + query_pos ; offsets = q@W_off ; logits = q@W_a
// ---------------------------------------------------------------------------
__global__ void __launch_bounds__(128) k_qproj(
    const float* __restrict__ query,  // (B,N,C)
    const float* __restrict__ qpos,   // (B,N,C)
    const float* __restrict__ Woff,   // (C,64)
    const float* __restrict__ boff,   // (64,)
    const float* __restrict__ Wa,     // (C,32)
    const float* __restrict__ ba)     // (32,)
{
    __shared__ float sq[16][C];
    const int t   = threadIdx.x;
    const int ro0 = blockIdx.x * 16;  // row = b*N + n

    #pragma unroll
    for (int i = 0; i < 16; i++) {
        int off = (ro0 + i) * C + t;
        sq[i][t] = query[off] + qpos[off];
    }
    __syncthreads();

    if (t < 96) {
        const float* Wp;
        int stride;
        float bias;
        if (t < 64) { Wp = Woff + t;        stride = 64; bias = __ldg(boff + t); }
        else        { Wp = Wa + (t - 64);   stride = 32; bias = __ldg(ba + t - 64); }

        float acc[16];
        #pragma unroll
        for (int r = 0; r < 16; r++) acc[r] = bias;

        #pragma unroll 4
        for (int k = 0; k < C; k++) {
            float w = __ldg(Wp + k * stride);
            #pragma unroll
            for (int r = 0; r < 16; r++) acc[r] = fmaf(sq[r][k], w, acc[r]);
        }
        #pragma unroll
        for (int r = 0; r < 16; r++) {
            int row = ro0 + r;
            if (t < 64) g_off[row * 64 + t]           = acc[r];
            else        g_logits[row * 32 + (t - 64)] = acc[r];
        }
    }
}

// ---------------------------------------------------------------------------
// Kernel 3: bilinear deformable sampling, ONE WARP PER QUERY.
// lane -> 4 channels (float4): head = lane>>3, channel quad = lane&7.
// Scalar sampling math issued once per warp (covers all 4 heads in lanes);
// each corner fetch is a single LDG.128.
// ---------------------------------------------------------------------------
__device__ __forceinline__ float4 fetch4(const float* __restrict__ vb, int yi, int xi) {
    bool valid = ((unsigned)yi < (unsigned)Hf) && ((unsigned)xi < (unsigned)Wf);
    int yc = min(max(yi, 0), Hf - 1);
    int xc = min(max(xi, 0), Wf - 1);
    float4 v = __ldg((const float4*)(vb + (yc * Wf + xc) * C));
    if (!valid) v = make_float4(0.f, 0.f, 0.f, 0.f);
    return v;
}

__global__ void __launch_bounds__(128) k_sample(
    const float* __restrict__ refpts,           // (S,B,N,D,2)
    const unsigned char* __restrict__ bev_mask) // (S,B,N,D), stride detected
{
    const unsigned FULL = 0xffffffffu;
    const int warp = threadIdx.x >> 5;
    const int lane = threadIdx.x & 31;
    const int row  = blockIdx.x * 4 + warp;  // b*N + n
    const int b    = row / N;
    const int n    = row % N;
    const int head = lane >> 3;
    const int sub  = lane & 7;

    // --- softmax over 8 points per head (8-lane segments) ---
    float l = __ldg(g_logits + row * 32 + lane);   // lane = head*8 + p
    float mx = l;
    #pragma unroll
    for (int o = 4; o > 0; o >>= 1) mx = fmaxf(mx, __shfl_xor_sync(FULL, mx, o, 8));
    float e = expf(l - mx);
    float ssum = e;
    #pragma unroll
    for (int o = 4; o > 0; o >>= 1) ssum += __shfl_xor_sync(FULL, ssum, o, 8);
    float aw = e / ssum;

    // --- offsets: lane holds pair for (head,p) = (lane>>3, lane&7) ---
    float2 oxy = __ldg((const float2*)(g_off + row * 64) + lane);

    // --- masks: lanes 0..5 probe camera s=lane; broadcast via ballot ---
    int sv = 0, hv = 0;
    unsigned occ = g_mask_occ;
    int st = (occ & 0x22u) ? 1 : ((occ & 0x1Cu) ? 4 : 8);
    if (lane < S) {
        int s = lane;
        long long e0 = ((long long)(s * B + 0) * N + n) * D;
        long long eb = ((long long)(s * B + b) * N + n) * D;
        #pragma unroll
        for (int d = 0; d < D; d++) {
            sv |= mask_nz(bev_mask, e0 + d, st);
            hv |= mask_nz(bev_mask, eb + d, st);
        }
    }
    unsigned selbits = __ballot_sync(FULL, (lane < S) && sv);
    unsigned hitbits = __ballot_sync(FULL, (lane < S) && hv);
    float inv_cnt = 1.0f / fmaxf((float)__popc(hitbits), 1.0f);

    // --- per-point constants for MY head, gathered by shuffle ---
    float ox[NP], oy[NP], wp[NP];
    #pragma unroll
    for (int p = 0; p < NP; p++) {
        int src = (head << 3) | p;
        ox[p] = __shfl_sync(FULL, oxy.x, src) - 0.5f;
        oy[p] = __shfl_sync(FULL, oxy.y, src) - 0.5f;
        wp[p] = __shfl_sync(FULL, aw,    src);
    }

    float4 acc = make_float4(0.f, 0.f, 0.f, 0.f);
    #pragma unroll
    for (int s = 0; s < S; s++) {
        if (!((selbits >> s) & 1u)) continue;  // warp-uniform
        const float* vb = g_vproj + (size_t)((s * B + b) * M) * C + head * 32 + sub * 4;
        const float4* rp4 = (const float4*)(refpts + (((size_t)(s * B + b) * N + n) * D) * 2);
        float4 r0 = __ldg(rp4), r1 = __ldg(rp4 + 1);
        float rx[D] = {r0.x, r0.z, r1.x, r1.z};
        float ry[D] = {r0.y, r0.w, r1.y, r1.w};

        #pragma unroll
        for (int p = 0; p < NP; p++) {
            int dz = p & 3;          // p -> dz = p % D (reshape order)
            float x = fmaf(rx[dz], (float)Wf, ox[p]);
            float y = fmaf(ry[dz], (float)Hf, oy[p]);
            float xf = floorf(x), yf = floorf(y);
            float wx1 = x - xf, wy1 = y - yf;
            int x0 = (int)xf, y0 = (int)yf;

            float4 f00 = fetch4(vb, y0,     x0);
            float4 f01 = fetch4(vb, y0,     x0 + 1);
            float4 f10 = fetch4(vb, y0 + 1, x0);
            float4 f11 = fetch4(vb, y0 + 1, x0 + 1);

            float wx0 = 1.0f - wx1, wy0 = 1.0f - wy1;
            float w00 = wy0 * wx0, w01 = wy0 * wx1, w10 = wy1 * wx0, w11 = wy1 * wx1;
            float bx = w00 * f00.x + w01 * f01.x + w10 * f10.x + w11 * f11.x;
            float by = w00 * f00.y + w01 * f01.y + w10 * f10.y + w11 * f11.y;
            float bz = w00 * f00.z + w01 * f01.z + w10 * f10.z + w11 * f11.z;
            float bw = w00 * f00.w + w01 * f01.w + w10 * f10.w + w11 * f11.w;
            acc.x = fmaf(wp[p], bx, acc.x);
            acc.y = fmaf(wp[p], by, acc.y);
            acc.z = fmaf(wp[p], bz, acc.z);
            acc.w = fmaf(wp[p], bw, acc.w);
        }
    }
    acc.x *= inv_cnt; acc.y *= inv_cnt; acc.z *= inv_cnt; acc.w *= inv_cnt;
    *(float4*)(g_slots + (size_t)row * C + lane * 4) = acc;
}

// ---------------------------------------------------------------------------
// Kernel 4: out = slots @ W_out + b_out + query
// ---------------------------------------------------------------------------
__global__ void __launch_bounds__(128) k_out(
    const float* __restrict__ query,  // (B,N,C)
    const float* __restrict__ Wo,     // (C,C)
    const float* __restrict__ bo,     // (C,)
    float* __restrict__ out)          // (B,N,C)
{
    __shared__ float sv[16][C];
    const int t   = threadIdx.x;
    const int ro0 = blockIdx.x * 16;

    #pragma unroll
    for (int i = 0; i < 16; i++) sv[i][t] = g_slots[(ro0 + i) * C + t];
    __syncthreads();

    float acc[16];
    const float bias = __ldg(bo + t);
    #pragma unroll
    for (int r = 0; r < 16; r++) acc[r] = bias;

    #pragma unroll 4
    for (int k = 0; k < C; k++) {
        float w = __ldg(Wo + k * C + t);
        #pragma unroll
        for (int r = 0; r < 16; r++) acc[r] = fmaf(sv[r][k], w, acc[r]);
    }
    #pragma unroll
    for (int r = 0; r < 16; r++) {
        int off = (ro0 + r) * C + t;
        out[off] = acc[r] + query[off];
    }
}

// ---------------------------------------------------------------------------
// Launch. Input order: query, key, value, query_pos, reference_points_cam,
// bev_mask, spatial_shapes, W_value, b_value, W_offsets, b_offsets,
// W_attn, b_attn, W_out, b_out.
// ---------------------------------------------------------------------------
extern "C" void kernel_launch(void* const* d_in, const int* in_sizes, int n_in,
                              void* d_out, int out_size)
{
    const float* query = (const float*)d_in[0];
    // d_in[1] = key: unused by the reference math
    const float* value = (const float*)d_in[2];
    const float* qpos  = (const float*)d_in[3];
    const float* refp  = (const float*)d_in[4];
    const unsigned char* mask = (const unsigned char*)d_in[5];
    // d_in[6] = spatial_shapes (static, hardcoded H=32, W=88)
    const float* Wv   = (const float*)d_in[7];
    const float* bv   = (const float*)d_in[8];
    const float* Woff = (const float*)d_in[9];
    const float* boff = (const float*)d_in[10];
    const float* Wa   = (const float*)d_in[11];
    const float* ba   = (const float*)d_in[12];
    const float* Wo   = (const float*)d_in[13];
    const float* bo   = (const float*)d_in[14];
    float* out = (float*)d_out;

    k_detect<<<64, 256>>>((const uint4*)mask);
    k_vproj <<<(S * B * M) / 16, 128>>>(value, Wv, bv);
    k_qproj <<<(B * N) / 16,     128>>>(query, qpos, Woff, boff, Wa, ba);
    k_sample<<<(B * N) / 4,      128>>>(refp, mask);
    k_out   <<<(B * N) / 16,     128>>>(query, Wo, bo, out);
}

// round 5
// speedup vs baseline: 1.9935x; 1.1214x over previous
#include <cuda_runtime.h>
#include <cuda_bf16.h>

// Problem constants (static per reference)
constexpr int B  = 2;
constexpr int S  = 6;
constexpr int N  = 10000;
constexpr int C  = 128;
constexpr int D  = 4;
constexpr int NH = 4;     // heads
constexpr int NP = 8;     // points
constexpr int Hf = 32;
constexpr int Wf = 88;
constexpr int M  = Hf * Wf;   // 2816
constexpr int MASK_ELEMS = S * B * N * D;  // 480000

// Scratch (device globals; no allocation allowed)
__device__ float    g_vproj [S * B * M * C];        // (s,b,m,c)
__device__ float    g_off   [B * N * NH * NP * 2];  // offsets (pixel units)
__device__ float    g_logits[B * N * NH * NP];      // attn logits
__device__ float    g_slots [B * N * C];            // masked-mean slots
__device__ unsigned g_mask_occ;                     // byte-position occupancy (OR-only: idempotent)

// ---------------------------------------------------------------------------
// Kernel 0: bev_mask dtype probe (byte-position occupancy mod 8).
// uint8 bools light positions 1/5; f32(1.0) lights 2,3,6,7; i32 lights 0,4.
// atomicOr accumulation is idempotent -> deterministic across graph replays.
// ---------------------------------------------------------------------------
__global__ void k_detect(const uint4* __restrict__ mask16)
{
    unsigned occ = 0u;
    const int nvec = MASK_ELEMS / 16;  // 30000
    for (int i = blockIdx.x * blockDim.x + threadIdx.x; i < nvec; i += gridDim.x * blockDim.x) {
        uint4 v = __ldg(mask16 + i);
        unsigned w[4] = {v.x, v.y, v.z, v.w};
        #pragma unroll
        for (int wi = 0; wi < 4; wi++) {
            int base = (wi * 4) & 7;
            #pragma unroll
            for (int k = 0; k < 4; k++)
                if ((w[wi] >> (k * 8)) & 0xFFu) occ |= 1u << ((base + k) & 7);
        }
    }
    #pragma unroll
    for (int o = 16; o > 0; o >>= 1) occ |= __shfl_xor_sync(0xffffffffu, occ, o);
    if ((threadIdx.x & 31) == 0 && occ) atomicOr(&g_mask_occ, occ);
}

__device__ __forceinline__ int mask_nz(const unsigned char* __restrict__ mask,
                                       long long elem, int st)
{
    const unsigned char* p = mask + elem * st;
    int v = 0;
    for (int j = 0; j < st; j++) v |= p[j];
    return v != 0;
}

// ---------------------------------------------------------------------------
// Kernel 1: value projection, 32 rows/block, 128 threads (thread = out chan).
// ---------------------------------------------------------------------------
__global__ void __launch_bounds__(128) k_vproj(
    const float* __restrict__ value,  // (S,M,B,C)
    const float* __restrict__ Wv,     // (C,C)
    const float* __restrict__ bv)     // (C,)
{
    __shared__ float sv[32][C];
    const int t   = threadIdx.x;
    const int ro0 = blockIdx.x * 32;  // row = (s*B+b)*M + m

    for (int idx = t; idx < 32 * 32; idx += 128) {
        int i  = idx >> 5;            // row 0..31
        int c4 = (idx & 31) * 4;
        int ro = ro0 + i;
        int sb = ro / M, m = ro % M;
        int s  = sb / B, b = sb % B;
        *(float4*)&sv[i][c4] =
            *(const float4*)(value + ((size_t)((s * M + m) * B + b) * C + c4));
    }
    __syncthreads();

    float acc[32];
    const float bias = __ldg(bv + t);
    #pragma unroll
    for (int r = 0; r < 32; r++) acc[r] = bias;

    #pragma unroll 2
    for (int k = 0; k < C; k++) {
        float w = __ldg(Wv + k * C + t);
        #pragma unroll
        for (int r = 0; r < 32; r++) acc[r] = fmaf(sv[r][k], w, acc[r]);
    }
    #pragma unroll
    for (int r = 0; r < 32; r++) g_vproj[(size_t)(ro0 + r) * C + t] = acc[r];
}

// ---------------------------------------------------------------------------
// Kernel 2: q = query + query_pos ; offsets = q@W_off ; logits = q@W_a
// 32 rows/block.
// ---------------------------------------------------------------------------
__global__ void __launch_bounds__(128) k_qproj(
    const float* __restrict__ query,  // (B,N,C)
    const float* __restrict__ qpos,   // (B,N,C)
    const float* __restrict__ Woff,   // (C,64)
    const float* __restrict__ boff,   // (64,)
    const float* __restrict__ Wa,     // (C,32)
    const float* __restrict__ ba)     // (32,)
{
    __shared__ float sq[32][C];
    const int t   = threadIdx.x;
    const int ro0 = blockIdx.x * 32;  // row = b*N + n

    for (int idx = t; idx < 32 * 32; idx += 128) {
        int i  = idx >> 5;
        int c4 = (idx & 31) * 4;
        size_t off = (size_t)(ro0 + i) * C + c4;
        float4 a = *(const float4*)(query + off);
        float4 p = *(const float4*)(qpos + off);
        a.x += p.x; a.y += p.y; a.z += p.z; a.w += p.w;
        *(float4*)&sq[i][c4] = a;
    }
    __syncthreads();

    if (t < 96) {
        const float* Wp;
        int stride;
        float bias;
        if (t < 64) { Wp = Woff + t;        stride = 64; bias = __ldg(boff + t); }
        else        { Wp = Wa + (t - 64);   stride = 32; bias = __ldg(ba + t - 64); }

        float acc[32];
        #pragma unroll
        for (int r = 0; r < 32; r++) acc[r] = bias;

        #pragma unroll 2
        for (int k = 0; k < C; k++) {
            float w = __ldg(Wp + k * stride);
            #pragma unroll
            for (int r = 0; r < 32; r++) acc[r] = fmaf(sq[r][k], w, acc[r]);
        }
        #pragma unroll
        for (int r = 0; r < 32; r++) {
            int row = ro0 + r;
            if (t < 64) g_off[row * 64 + t]           = acc[r];
            else        g_logits[row * 32 + (t - 64)] = acc[r];
        }
    }
}

// ---------------------------------------------------------------------------
// Kernel 3: bilinear deformable sampling, ONE WARP PER QUERY.
// lane -> 4 channels (float4): head = lane>>3, quad = lane&7.
// Warp-uniform fast path: fully in-bounds 2x2 -> one base IMAD + 4 LDG.128
// with constant immediate offsets. Boundary path clamps per corner.
// ---------------------------------------------------------------------------
__device__ __forceinline__ float4 fetch4(const float* __restrict__ vb, int yi, int xi) {
    bool valid = ((unsigned)yi < (unsigned)Hf) && ((unsigned)xi < (unsigned)Wf);
    int yc = min(max(yi, 0), Hf - 1);
    int xc = min(max(xi, 0), Wf - 1);
    float4 v = __ldg((const float4*)(vb + (yc * Wf + xc) * C));
    if (!valid) v = make_float4(0.f, 0.f, 0.f, 0.f);
    return v;
}

__global__ void __launch_bounds__(128) k_sample(
    const float* __restrict__ refpts,           // (S,B,N,D,2)
    const unsigned char* __restrict__ bev_mask) // (S,B,N,D), stride detected
{
    const unsigned FULL = 0xffffffffu;
    const int warp = threadIdx.x >> 5;
    const int lane = threadIdx.x & 31;
    const int row  = blockIdx.x * 4 + warp;  // b*N + n
    const int b    = row / N;
    const int n    = row % N;
    const int head = lane >> 3;
    const int sub  = lane & 7;

    // softmax over 8 points per head (8-lane segments)
    float l = __ldg(g_logits + row * 32 + lane);   // lane = head*8 + p
    float mx = l;
    #pragma unroll
    for (int o = 4; o > 0; o >>= 1) mx = fmaxf(mx, __shfl_xor_sync(FULL, mx, o, 8));
    float e = expf(l - mx);
    float ssum = e;
    #pragma unroll
    for (int o = 4; o > 0; o >>= 1) ssum += __shfl_xor_sync(FULL, ssum, o, 8);
    float aw = e / ssum;

    // offsets: lane holds pair for (head,p) = (lane>>3, lane&7)
    float2 oxy = __ldg((const float2*)(g_off + row * 64) + lane);

    // masks: lanes 0..5 probe camera s=lane; broadcast via ballot
    int sv = 0, hv = 0;
    unsigned occ = g_mask_occ;
    int st = (occ & 0x22u) ? 1 : ((occ & 0x1Cu) ? 4 : 8);
    if (lane < S) {
        int s = lane;
        long long e0 = ((long long)(s * B + 0) * N + n) * D;
        long long eb = ((long long)(s * B + b) * N + n) * D;
        #pragma unroll
        for (int d = 0; d < D; d++) {
            sv |= mask_nz(bev_mask, e0 + d, st);
            hv |= mask_nz(bev_mask, eb + d, st);
        }
    }
    unsigned selbits = __ballot_sync(FULL, (lane < S) && sv);
    unsigned hitbits = __ballot_sync(FULL, (lane < S) && hv);
    float inv_cnt = 1.0f / fmaxf((float)__popc(hitbits), 1.0f);

    // per-point constants for MY head, gathered by shuffle
    float ox[NP], oy[NP], wp[NP];
    #pragma unroll
    for (int p = 0; p < NP; p++) {
        int src = (head << 3) | p;
        ox[p] = __shfl_sync(FULL, oxy.x, src) - 0.5f;
        oy[p] = __shfl_sync(FULL, oxy.y, src) - 0.5f;
        wp[p] = __shfl_sync(FULL, aw,    src);
    }

    float4 acc = make_float4(0.f, 0.f, 0.f, 0.f);
    #pragma unroll
    for (int s = 0; s < S; s++) {
        if (!((selbits >> s) & 1u)) continue;  // warp-uniform
        const float* vb = g_vproj + (size_t)((s * B + b) * M) * C + head * 32 + sub * 4;
        const float4* rp4 = (const float4*)(refpts + (((size_t)(s * B + b) * N + n) * D) * 2);
        float4 r0 = __ldg(rp4), r1 = __ldg(rp4 + 1);
        float xb[D] = {r0.x * Wf, r0.z * Wf, r1.x * Wf, r1.z * Wf};
        float yb[D] = {r0.y * Hf, r0.w * Hf, r1.y * Hf, r1.w * Hf};

        #pragma unroll
        for (int p = 0; p < NP; p++) {
            int dz = p & 3;          // p -> dz = p % D (reshape order)
            float x = xb[dz] + ox[p];
            float y = yb[dz] + oy[p];
            float xf = floorf(x), yf = floorf(y);
            float wx1 = x - xf, wy1 = y - yf;
            int x0 = (int)xf, y0 = (int)yf;

            float4 f00, f01, f10, f11;
            // warp-uniform condition: no divergence
            if (((unsigned)x0 < (unsigned)(Wf - 1)) & ((unsigned)y0 < (unsigned)(Hf - 1))) {
                const float4* base = (const float4*)(vb + (y0 * Wf + x0) * C);
                f00 = __ldg(base);
                f01 = __ldg(base + (C / 4));               // +512B
                f10 = __ldg(base + (Wf * C / 4));          // +45056B
                f11 = __ldg(base + ((Wf + 1) * C / 4));    // +45568B
            } else {
                f00 = fetch4(vb, y0,     x0);
                f01 = fetch4(vb, y0,     x0 + 1);
                f10 = fetch4(vb, y0 + 1, x0);
                f11 = fetch4(vb, y0 + 1, x0 + 1);
            }

            float wx0 = 1.0f - wx1, wy0 = 1.0f - wy1;
            float w00 = wy0 * wx0, w01 = wy0 * wx1, w10 = wy1 * wx0, w11 = wy1 * wx1;
            float bx = w00 * f00.x + w01 * f01.x + w10 * f10.x + w11 * f11.x;
            float by = w00 * f00.y + w01 * f01.y + w10 * f10.y + w11 * f11.y;
            float bz = w00 * f00.z + w01 * f01.z + w10 * f10.z + w11 * f11.z;
            float bw = w00 * f00.w + w01 * f01.w + w10 * f10.w + w11 * f11.w;
            acc.x = fmaf(wp[p], bx, acc.x);
            acc.y = fmaf(wp[p], by, acc.y);
            acc.z = fmaf(wp[p], bz, acc.z);
            acc.w = fmaf(wp[p], bw, acc.w);
        }
    }
    acc.x *= inv_cnt; acc.y *= inv_cnt; acc.z *= inv_cnt; acc.w *= inv_cnt;
    *(float4*)(g_slots + (size_t)row * C + lane * 4) = acc;
}

// ---------------------------------------------------------------------------
// Kernel 4: out = slots @ W_out + b_out + query. 32 rows/block.
// ---------------------------------------------------------------------------
__global__ void __launch_bounds__(128) k_out(
    const float* __restrict__ query,  // (B,N,C)
    const float* __restrict__ Wo,     // (C,C)
    const float* __restrict__ bo,     // (C,)
    float* __restrict__ out)          // (B,N,C)
{
    __shared__ float sv[32][C];
    const int t   = threadIdx.x;
    const int ro0 = blockIdx.x * 32;

    for (int idx = t; idx < 32 * 32; idx += 128) {
        int i  = idx >> 5;
        int c4 = (idx & 31) * 4;
        *(float4*)&sv[i][c4] = *(const float4*)(g_slots + (size_t)(ro0 + i) * C + c4);
    }
    __syncthreads();

    float acc[32];
    const float bias = __ldg(bo + t);
    #pragma unroll
    for (int r = 0; r < 32; r++) acc[r] = bias;

    #pragma unroll 2
    for (int k = 0; k < C; k++) {
        float w = __ldg(Wo + k * C + t);
        #pragma unroll
        for (int r = 0; r < 32; r++) acc[r] = fmaf(sv[r][k], w, acc[r]);
    }
    #pragma unroll
    for (int r = 0; r < 32; r++) {
        size_t off = (size_t)(ro0 + r) * C + t;
        out[off] = acc[r] + query[off];
    }
}

// ---------------------------------------------------------------------------
// Launch. Input order: query, key, value, query_pos, reference_points_cam,
// bev_mask, spatial_shapes, W_value, b_value, W_offsets, b_offsets,
// W_attn, b_attn, W_out, b_out.
// ---------------------------------------------------------------------------
extern "C" void kernel_launch(void* const* d_in, const int* in_sizes, int n_in,
                              void* d_out, int out_size)
{
    const float* query = (const float*)d_in[0];
    // d_in[1] = key: unused by the reference math
    const float* value = (const float*)d_in[2];
    const float* qpos  = (const float*)d_in[3];
    const float* refp  = (const float*)d_in[4];
    const unsigned char* mask = (const unsigned char*)d_in[5];
    // d_in[6] = spatial_shapes (static, hardcoded H=32, W=88)
    const float* Wv   = (const float*)d_in[7];
    const float* bv   = (const float*)d_in[8];
    const float* Woff = (const float*)d_in[9];
    const float* boff = (const float*)d_in[10];
    const float* Wa   = (const float*)d_in[11];
    const float* ba   = (const float*)d_in[12];
    const float* Wo   = (const float*)d_in[13];
    const float* bo   = (const float*)d_in[14];
    float* out = (float*)d_out;

    k_detect<<<64, 256>>>((const uint4*)mask);
    k_vproj <<<(S * B * M) / 32, 128>>>(value, Wv, bv);
    k_qproj <<<(B * N) / 32,     128>>>(query, qpos, Woff, boff, Wa, ba);
    k_sample<<<(B * N) / 4,      128>>>(refp, mask);
    k_out   <<<(B * N) / 32,     128>>>(query, Wo, bo, out);
}

// round 7
// speedup vs baseline: 2.3132x; 1.1604x over previous
#include <cuda_runtime.h>
#include <cuda_fp16.h>

// Problem constants (static per reference)
constexpr int B  = 2;
constexpr int S  = 6;
constexpr int N  = 10000;
constexpr int C  = 128;
constexpr int D  = 4;
constexpr int NH = 4;     // heads
constexpr int NP = 8;     // points
constexpr int Hf = 32;
constexpr int Wf = 88;
constexpr int M  = Hf * Wf;   // 2816
constexpr int MASK_ELEMS = S * B * N * D;  // 480000

// Scratch (device globals; no allocation allowed)
__device__ __half   g_vproj [S * B * M * C];        // (s,b,m,c)  fp16
__device__ float    g_off   [B * N * NH * NP * 2];  // offsets (pixel units)
__device__ float    g_logits[B * N * NH * NP];      // attn logits
__device__ float    g_slots [B * N * C];            // masked-mean slots
__device__ unsigned g_mask_occ;                     // byte-position occupancy (OR-only: idempotent)

// ---------------------------------------------------------------------------
// Kernel 0: bev_mask dtype probe (byte-position occupancy mod 8).
// uint8 bools light positions 1/5; f32(1.0) lights 2,3,6,7; i32 lights 0,4.
// atomicOr accumulation is idempotent -> deterministic across graph replays.
// ---------------------------------------------------------------------------
__global__ void k_detect(const uint4* __restrict__ mask16)
{
    unsigned occ = 0u;
    const int nvec = MASK_ELEMS / 16;  // 30000
    for (int i = blockIdx.x * blockDim.x + threadIdx.x; i < nvec; i += gridDim.x * blockDim.x) {
        uint4 v = __ldg(mask16 + i);
        unsigned w[4] = {v.x, v.y, v.z, v.w};
        #pragma unroll
        for (int wi = 0; wi < 4; wi++) {
            int base = (wi * 4) & 7;
            #pragma unroll
            for (int k = 0; k < 4; k++)
                if ((w[wi] >> (k * 8)) & 0xFFu) occ |= 1u << ((base + k) & 7);
        }
    }
    #pragma unroll
    for (int o = 16; o > 0; o >>= 1) occ |= __shfl_xor_sync(0xffffffffu, occ, o);
    if ((threadIdx.x & 31) == 0 && occ) atomicOr(&g_mask_occ, occ);
}

__device__ __forceinline__ int mask_nz(const unsigned char* __restrict__ mask,
                                       long long elem, int st)
{
    const unsigned char* p = mask + elem * st;
    int v = 0;
    for (int j = 0; j < st; j++) v |= p[j];
    return v != 0;
}

// ---------------------------------------------------------------------------
// Kernel 1: value projection, 32 rows/block, 128 threads (thread = out chan).
// Output stored fp16. Inner loop k-unrolled x4 with LDS.128.
// ---------------------------------------------------------------------------
__global__ void __launch_bounds__(128) k_vproj(
    const float* __restrict__ value,  // (S,M,B,C)
    const float* __restrict__ Wv,     // (C,C)
    const float* __restrict__ bv)     // (C,)
{
    __shared__ float sv[32][C];
    const int t   = threadIdx.x;
    const int ro0 = blockIdx.x * 32;  // row = (s*B+b)*M + m

    for (int idx = t; idx < 32 * 32; idx += 128) {
        int i  = idx >> 5;            // row 0..31
        int c4 = (idx & 31) * 4;
        int ro = ro0 + i;
        int sb = ro / M, m = ro % M;
        int s  = sb / B, b = sb % B;
        *(float4*)&sv[i][c4] =
            *(const float4*)(value + ((size_t)((s * M + m) * B + b) * C + c4));
    }
    __syncthreads();

    float acc[32];
    const float bias = __ldg(bv + t);
    #pragma unroll
    for (int r = 0; r < 32; r++) acc[r] = bias;

    for (int k = 0; k < C; k += 4) {
        float w0 = __ldg(Wv + (k + 0) * C + t);
        float w1 = __ldg(Wv + (k + 1) * C + t);
        float w2 = __ldg(Wv + (k + 2) * C + t);
        float w3 = __ldg(Wv + (k + 3) * C + t);
        #pragma unroll
        for (int r = 0; r < 32; r++) {
            float4 s4 = *(const float4*)&sv[r][k];
            acc[r] = fmaf(s4.x, w0, acc[r]);
            acc[r] = fmaf(s4.y, w1, acc[r]);
            acc[r] = fmaf(s4.z, w2, acc[r]);
            acc[r] = fmaf(s4.w, w3, acc[r]);
        }
    }
    #pragma unroll
    for (int r = 0; r < 32; r++)
        g_vproj[(size_t)(ro0 + r) * C + t] = __float2half_rn(acc[r]);
}

// ---------------------------------------------------------------------------
// Kernel 2: q = query + query_pos ; offsets = q@W_off ; logits = q@W_a
// 32 rows/block, k-unrolled x4.
// ---------------------------------------------------------------------------
__global__ void __launch_bounds__(128) k_qproj(
    const float* __restrict__ query,  // (B,N,C)
    const float* __restrict__ qpos,   // (B,N,C)
    const float* __restrict__ Woff,   // (C,64)
    const float* __restrict__ boff,   // (64,)
    const float* __restrict__ Wa,     // (C,32)
    const float* __restrict__ ba)     // (32,)
{
    __shared__ float sq[32][C];
    const int t   = threadIdx.x;
    const int ro0 = blockIdx.x * 32;  // row = b*N + n

    for (int idx = t; idx < 32 * 32; idx += 128) {
        int i  = idx >> 5;
        int c4 = (idx & 31) * 4;
        size_t off = (size_t)(ro0 + i) * C + c4;
        float4 a = *(const float4*)(query + off);
        float4 p = *(const float4*)(qpos + off);
        a.x += p.x; a.y += p.y; a.z += p.z; a.w += p.w;
        *(float4*)&sq[i][c4] = a;
    }
    __syncthreads();

    if (t < 96) {
        const float* Wp;
        int stride;
        float bias;
        if (t < 64) { Wp = Woff + t;        stride = 64; bias = __ldg(boff + t); }
        else        { Wp = Wa + (t - 64);   stride = 32; bias = __ldg(ba + t - 64); }

        float acc[32];
        #pragma unroll
        for (int r = 0; r < 32; r++) acc[r] = bias;

        for (int k = 0; k < C; k += 4) {
            float w0 = __ldg(Wp + (k + 0) * stride);
            float w1 = __ldg(Wp + (k + 1) * stride);
            float w2 = __ldg(Wp + (k + 2) * stride);
            float w3 = __ldg(Wp + (k + 3) * stride);
            #pragma unroll
            for (int r = 0; r < 32; r++) {
                float4 s4 = *(const float4*)&sq[r][k];
                acc[r] = fmaf(s4.x, w0, acc[r]);
                acc[r] = fmaf(s4.y, w1, acc[r]);
                acc[r] = fmaf(s4.z, w2, acc[r]);
                acc[r] = fmaf(s4.w, w3, acc[r]);
            }
        }
        #pragma unroll
        for (int r = 0; r < 32; r++) {
            int row = ro0 + r;
            if (t < 64) g_off[row * 64 + t]           = acc[r];
            else        g_logits[row * 32 + (t - 64)] = acc[r];
        }
    }
}

// ---------------------------------------------------------------------------
// Kernel 3: bilinear deformable sampling, ONE WARP PER QUERY, fp16 values.
// lane -> 4 channels (2x half2, LDG.64): head = lane>>3, quad = lane&7.
// Bilinear in half2 arithmetic; accumulation over points/cameras in fp32.
// ---------------------------------------------------------------------------
__device__ __forceinline__ uint2 fetchh(const __half* __restrict__ vb, int yi, int xi) {
    bool valid = ((unsigned)yi < (unsigned)Hf) && ((unsigned)xi < (unsigned)Wf);
    int yc = min(max(yi, 0), Hf - 1);
    int xc = min(max(xi, 0), Wf - 1);
    uint2 v = __ldg((const uint2*)(vb + (yc * Wf + xc) * C));
    if (!valid) v = make_uint2(0u, 0u);
    return v;
}

__global__ void __launch_bounds__(128) k_sample(
    const float* __restrict__ refpts,           // (S,B,N,D,2)
    const unsigned char* __restrict__ bev_mask) // (S,B,N,D), stride detected
{
    const unsigned FULL = 0xffffffffu;
    const int warp = threadIdx.x >> 5;
    const int lane = threadIdx.x & 31;
    const int row  = blockIdx.x * 4 + warp;  // b*N + n
    const int b    = row / N;
    const int n    = row % N;
    const int head = lane >> 3;
    const int sub  = lane & 7;

    // softmax over 8 points per head (8-lane segments)
    float l = __ldg(g_logits + row * 32 + lane);   // lane = head*8 + p
    float mx = l;
    #pragma unroll
    for (int o = 4; o > 0; o >>= 1) mx = fmaxf(mx, __shfl_xor_sync(FULL, mx, o, 8));
    float e = expf(l - mx);
    float ssum = e;
    #pragma unroll
    for (int o = 4; o > 0; o >>= 1) ssum += __shfl_xor_sync(FULL, ssum, o, 8);
    float aw = e / ssum;

    // offsets: lane holds pair for (head,p) = (lane>>3, lane&7)
    float2 oxy = __ldg((const float2*)(g_off + row * 64) + lane);

    // masks: lanes 0..5 probe camera s=lane; broadcast via ballot
    int sv = 0, hv = 0;
    unsigned occ = g_mask_occ;
    int st = (occ & 0x22u) ? 1 : ((occ & 0x1Cu) ? 4 : 8);
    if (lane < S) {
        int s = lane;
        long long e0 = ((long long)(s * B + 0) * N + n) * D;
        long long eb = ((long long)(s * B + b) * N + n) * D;
        #pragma unroll
        for (int d = 0; d < D; d++) {
            sv |= mask_nz(bev_mask, e0 + d, st);
            hv |= mask_nz(bev_mask, eb + d, st);
        }
    }
    unsigned selbits = __ballot_sync(FULL, (lane < S) && sv);
    unsigned hitbits = __ballot_sync(FULL, (lane < S) && hv);
    float inv_cnt = 1.0f / fmaxf((float)__popc(hitbits), 1.0f);

    // per-point constants for MY head, gathered by shuffle
    float ox[NP], oy[NP], wp[NP];
    #pragma unroll
    for (int p = 0; p < NP; p++) {
        int src = (head << 3) | p;
        ox[p] = __shfl_sync(FULL, oxy.x, src) - 0.5f;
        oy[p] = __shfl_sync(FULL, oxy.y, src) - 0.5f;
        wp[p] = __shfl_sync(FULL, aw,    src);
    }

    float4 acc = make_float4(0.f, 0.f, 0.f, 0.f);
    #pragma unroll
    for (int s = 0; s < S; s++) {
        if (!((selbits >> s) & 1u)) continue;  // warp-uniform
        const __half* vb = g_vproj + (size_t)((s * B + b) * M) * C + head * 32 + sub * 4;
        const float4* rp4 = (const float4*)(refpts + (((size_t)(s * B + b) * N + n) * D) * 2);
        float4 r0 = __ldg(rp4), r1 = __ldg(rp4 + 1);
        float xb[D] = {r0.x * Wf, r0.z * Wf, r1.x * Wf, r1.z * Wf};
        float yb[D] = {r0.y * Hf, r0.w * Hf, r1.y * Hf, r1.w * Hf};

        #pragma unroll
        for (int p = 0; p < NP; p++) {
            int dz = p & 3;          // p -> dz = p % D (reshape order)
            float x = xb[dz] + ox[p];
            float y = yb[dz] + oy[p];
            float xf = floorf(x), yf = floorf(y);
            float wx1 = x - xf, wy1 = y - yf;
            int x0 = (int)xf, y0 = (int)yf;

            uint2 u00, u01, u10, u11;
            // warp-uniform condition: no divergence
            if (((unsigned)x0 < (unsigned)(Wf - 1)) & ((unsigned)y0 < (unsigned)(Hf - 1))) {
                const uint2* base = (const uint2*)(vb + (y0 * Wf + x0) * C);
                u00 = __ldg(base);
                u01 = __ldg(base + (C / 4));               // +1 pixel (128 halves = 32 uint2)
                u10 = __ldg(base + (Wf * C / 4));          // +1 row
                u11 = __ldg(base + ((Wf + 1) * C / 4));
            } else {
                u00 = fetchh(vb, y0,     x0);
                u01 = fetchh(vb, y0,     x0 + 1);
                u10 = fetchh(vb, y0 + 1, x0);
                u11 = fetchh(vb, y0 + 1, x0 + 1);
            }

            float wx0 = 1.0f - wx1, wy0 = 1.0f - wy1;
            __half2 hw00 = __float2half2_rn(wy0 * wx0);
            __half2 hw01 = __float2half2_rn(wy0 * wx1);
            __half2 hw10 = __float2half2_rn(wy1 * wx0);
            __half2 hw11 = __float2half2_rn(wy1 * wx1);

            __half2 sa = __hmul2(*(__half2*)&u00.x, hw00);
            sa = __hfma2(*(__half2*)&u01.x, hw01, sa);
            sa = __hfma2(*(__half2*)&u10.x, hw10, sa);
            sa = __hfma2(*(__half2*)&u11.x, hw11, sa);
            __half2 sb = __hmul2(*(__half2*)&u00.y, hw00);
            sb = __hfma2(*(__half2*)&u01.y, hw01, sb);
            sb = __hfma2(*(__half2*)&u10.y, hw10, sb);
            sb = __hfma2(*(__half2*)&u11.y, hw11, sb);

            float2 fa = __half22float2(sa);
            float2 fb = __half22float2(sb);
            acc.x = fmaf(wp[p], fa.x, acc.x);
            acc.y = fmaf(wp[p], fa.y, acc.y);
            acc.z = fmaf(wp[p], fb.x, acc.z);
            acc.w = fmaf(wp[p], fb.y, acc.w);
        }
    }
    acc.x *= inv_cnt; acc.y *= inv_cnt; acc.z *= inv_cnt; acc.w *= inv_cnt;
    *(float4*)(g_slots + (size_t)row * C + lane * 4) = acc;
}

// ---------------------------------------------------------------------------
// Kernel 4: out = slots @ W_out + b_out + query. 32 rows/block, k-unroll x4.
// ---------------------------------------------------------------------------
__global__ void __launch_bounds__(128) k_out(
    const float* __restrict__ query,  // (B,N,C)
    const float* __restrict__ Wo,     // (C,C)
    const float* __restrict__ bo,     // (C,)
    float* __restrict__ out)          // (B,N,C)
{
    __shared__ float sv[32][C];
    const int t   = threadIdx.x;
    const int ro0 = blockIdx.x * 32;

    for (int idx = t; idx < 32 * 32; idx += 128) {
        int i  = idx >> 5;
        int c4 = (idx & 31) * 4;
        *(float4*)&sv[i][c4] = *(const float4*)(g_slots + (size_t)(ro0 + i) * C + c4);
    }
    __syncthreads();

    float acc[32];
    const float bias = __ldg(bo + t);
    #pragma unroll
    for (int r = 0; r < 32; r++) acc[r] = bias;

    for (int k = 0; k < C; k += 4) {
        float w0 = __ldg(Wo + (k + 0) * C + t);
        float w1 = __ldg(Wo + (k + 1) * C + t);
        float w2 = __ldg(Wo + (k + 2) * C + t);
        float w3 = __ldg(Wo + (k + 3) * C + t);
        #pragma unroll
        for (int r = 0; r < 32; r++) {
            float4 s4 = *(const float4*)&sv[r][k];
            acc[r] = fmaf(s4.x, w0, acc[r]);
            acc[r] = fmaf(s4.y, w1, acc[r]);
            acc[r] = fmaf(s4.z, w2, acc[r]);
            acc[r] = fmaf(s4.w, w3, acc[r]);
        }
    }
    #pragma unroll
    for (int r = 0; r < 32; r++) {
        size_t off = (size_t)(ro0 + r) * C + t;
        out[off] = acc[r] + query[off];
    }
}

// ---------------------------------------------------------------------------
// Launch. Input order: query, key, value, query_pos, reference_points_cam,
// bev_mask, spatial_shapes, W_value, b_value, W_offsets, b_offsets,
// W_attn, b_attn, W_out, b_out.
// ---------------------------------------------------------------------------
extern "C" void kernel_launch(void* const* d_in, const int* in_sizes, int n_in,
                              void* d_out, int out_size)
{
    const float* query = (const float*)d_in[0];
    // d_in[1] = key: unused by the reference math
    const float* value = (const float*)d_in[2];
    const float* qpos  = (const float*)d_in[3];
    const float* refp  = (const float*)d_in[4];
    const unsigned char* mask = (const unsigned char*)d_in[5];
    // d_in[6] = spatial_shapes (static, hardcoded H=32, W=88)
    const float* Wv   = (const float*)d_in[7];
    const float* bv   = (const float*)d_in[8];
    const float* Woff = (const float*)d_in[9];
    const float* boff = (const float*)d_in[10];
    const float* Wa   = (const float*)d_in[11];
    const float* ba   = (const float*)d_in[12];
    const float* Wo   = (const float*)d_in[13];
    const float* bo   = (const float*)d_in[14];
    float* out = (float*)d_out;

    k_detect<<<64, 256>>>((const uint4*)mask);
    k_vproj <<<(S * B * M) / 32, 128>>>(value, Wv, bv);
    k_qproj <<<(B * N) / 32,     128>>>(query, qpos, Woff, boff, Wa, ba);
    k_sample<<<(B * N) / 4,      128>>>(refp, mask);
    k_out   <<<(B * N) / 32,     128>>>(query, Wo, bo, out);
}

// round 9
// speedup vs baseline: 2.3799x; 1.0289x over previous
#include <cuda_runtime.h>
#include <cuda_fp16.h>

// Problem constants (static per reference)
constexpr int B  = 2;
constexpr int S  = 6;
constexpr int N  = 10000;
constexpr int C  = 128;
constexpr int D  = 4;
constexpr int NH = 4;     // heads
constexpr int NP = 8;     // points
constexpr int Hf = 32;
constexpr int Wf = 88;
constexpr int M  = Hf * Wf;   // 2816
constexpr int MASK_ELEMS = S * B * N * D;  // 480000

// Scratch (device globals; no allocation allowed)
__device__ __half   g_vproj [S * B * M * C];        // (s,b,m,c)  fp16
__device__ float    g_off   [B * N * NH * NP * 2];  // offsets (pixel units)
__device__ float    g_logits[B * N * NH * NP];      // attn logits
__device__ float    g_slots [B * N * C];            // masked-mean slots
__device__ unsigned g_mask_occ;                     // byte-position occupancy (OR-only: idempotent)

// ---------------------------------------------------------------------------
// Kernel 0: bev_mask dtype probe (byte-position occupancy mod 8).
// uint8 bools light positions 1/5; f32(1.0) lights 2,3,6,7; i32 lights 0,4.
// atomicOr accumulation is idempotent -> deterministic across graph replays.
// ---------------------------------------------------------------------------
__global__ void k_detect(const uint4* __restrict__ mask16)
{
    unsigned occ = 0u;
    const int nvec = MASK_ELEMS / 16;  // 30000
    for (int i = blockIdx.x * blockDim.x + threadIdx.x; i < nvec; i += gridDim.x * blockDim.x) {
        uint4 v = __ldg(mask16 + i);
        unsigned w[4] = {v.x, v.y, v.z, v.w};
        #pragma unroll
        for (int wi = 0; wi < 4; wi++) {
            int base = (wi * 4) & 7;
            #pragma unroll
            for (int k = 0; k < 4; k++)
                if ((w[wi] >> (k * 8)) & 0xFFu) occ |= 1u << ((base + k) & 7);
        }
    }
    #pragma unroll
    for (int o = 16; o > 0; o >>= 1) occ |= __shfl_xor_sync(0xffffffffu, occ, o);
    if ((threadIdx.x & 31) == 0 && occ) atomicOr(&g_mask_occ, occ);
}

__device__ __forceinline__ int mask_nz(const unsigned char* __restrict__ mask,
                                       long long elem, int st)
{
    const unsigned char* p = mask + elem * st;
    int v = 0;
    for (int j = 0; j < st; j++) v |= p[j];
    return v != 0;
}

// ---------------------------------------------------------------------------
// Kernel 1: value projection, 32 rows/block, 128 threads (thread = out chan).
// Output stored fp16. Inner loop k-unrolled x4 with LDS.128.
// ---------------------------------------------------------------------------
__global__ void __launch_bounds__(128) k_vproj(
    const float* __restrict__ value,  // (S,M,B,C)
    const float* __restrict__ Wv,     // (C,C)
    const float* __restrict__ bv)     // (C,)
{
    __shared__ float sv[32][C];
    const int t   = threadIdx.x;
    const int ro0 = blockIdx.x * 32;  // row = (s*B+b)*M + m

    for (int idx = t; idx < 32 * 32; idx += 128) {
        int i  = idx >> 5;            // row 0..31
        int c4 = (idx & 31) * 4;
        int ro = ro0 + i;
        int sb = ro / M, m = ro % M;
        int s  = sb / B, b = sb % B;
        *(float4*)&sv[i][c4] =
            *(const float4*)(value + ((size_t)((s * M + m) * B + b) * C + c4));
    }
    __syncthreads();

    float acc[32];
    const float bias = __ldg(bv + t);
    #pragma unroll
    for (int r = 0; r < 32; r++) acc[r] = bias;

    for (int k = 0; k < C; k += 4) {
        float w0 = __ldg(Wv + (k + 0) * C + t);
        float w1 = __ldg(Wv + (k + 1) * C + t);
        float w2 = __ldg(Wv + (k + 2) * C + t);
        float w3 = __ldg(Wv + (k + 3) * C + t);
        #pragma unroll
        for (int r = 0; r < 32; r++) {
            float4 s4 = *(const float4*)&sv[r][k];
            acc[r] = fmaf(s4.x, w0, acc[r]);
            acc[r] = fmaf(s4.y, w1, acc[r]);
            acc[r] = fmaf(s4.z, w2, acc[r]);
            acc[r] = fmaf(s4.w, w3, acc[r]);
        }
    }
    #pragma unroll
    for (int r = 0; r < 32; r++)
        g_vproj[(size_t)(ro0 + r) * C + t] = __float2half_rn(acc[r]);
}

// ---------------------------------------------------------------------------
// Kernel 2: q = query + query_pos ; offsets = q@W_off ; logits = q@W_a
// 32 rows/block, k-unrolled x4.
// ---------------------------------------------------------------------------
__global__ void __launch_bounds__(128) k_qproj(
    const float* __restrict__ query,  // (B,N,C)
    const float* __restrict__ qpos,   // (B,N,C)
    const float* __restrict__ Woff,   // (C,64)
    const float* __restrict__ boff,   // (64,)
    const float* __restrict__ Wa,     // (C,32)
    const float* __restrict__ ba)     // (32,)
{
    __shared__ float sq[32][C];
    const int t   = threadIdx.x;
    const int ro0 = blockIdx.x * 32;  // row = b*N + n

    for (int idx = t; idx < 32 * 32; idx += 128) {
        int i  = idx >> 5;
        int c4 = (idx & 31) * 4;
        size_t off = (size_t)(ro0 + i) * C + c4;
        float4 a = *(const float4*)(query + off);
        float4 p = *(const float4*)(qpos + off);
        a.x += p.x; a.y += p.y; a.z += p.z; a.w += p.w;
        *(float4*)&sq[i][c4] = a;
    }
    __syncthreads();

    if (t < 96) {
        const float* Wp;
        int stride;
        float bias;
        if (t < 64) { Wp = Woff + t;        stride = 64; bias = __ldg(boff + t); }
        else        { Wp = Wa + (t - 64);   stride = 32; bias = __ldg(ba + t - 64); }

        float acc[32];
        #pragma unroll
        for (int r = 0; r < 32; r++) acc[r] = bias;

        for (int k = 0; k < C; k += 4) {
            float w0 = __ldg(Wp + (k + 0) * stride);
            float w1 = __ldg(Wp + (k + 1) * stride);
            float w2 = __ldg(Wp + (k + 2) * stride);
            float w3 = __ldg(Wp + (k + 3) * stride);
            #pragma unroll
            for (int r = 0; r < 32; r++) {
                float4 s4 = *(const float4*)&sq[r][k];
                acc[r] = fmaf(s4.x, w0, acc[r]);
                acc[r] = fmaf(s4.y, w1, acc[r]);
                acc[r] = fmaf(s4.z, w2, acc[r]);
                acc[r] = fmaf(s4.w, w3, acc[r]);
            }
        }
        #pragma unroll
        for (int r = 0; r < 32; r++) {
            int row = ro0 + r;
            if (t < 64) g_off[row * 64 + t]           = acc[r];
            else        g_logits[row * 32 + (t - 64)] = acc[r];
        }
    }
}

// ---------------------------------------------------------------------------
// Kernel 3: bilinear deformable sampling, ONE WARP PER QUERY, fp16 values.
// Per-point constants live in SHARED memory (broadcast reads) instead of
// 24 registers -> regs freed for load batching, occupancy up.
// ---------------------------------------------------------------------------
__device__ __forceinline__ uint2 fetchh(const __half* __restrict__ vb, int yi, int xi) {
    bool valid = ((unsigned)yi < (unsigned)Hf) && ((unsigned)xi < (unsigned)Wf);
    int yc = min(max(yi, 0), Hf - 1);
    int xc = min(max(xi, 0), Wf - 1);
    uint2 v = __ldg((const uint2*)(vb + (yc * Wf + xc) * C));
    if (!valid) v = make_uint2(0u, 0u);
    return v;
}

__global__ void __launch_bounds__(128, 10) k_sample(
    const float* __restrict__ refpts,           // (S,B,N,D,2)
    const unsigned char* __restrict__ bev_mask) // (S,B,N,D), stride detected
{
    const unsigned FULL = 0xffffffffu;
    const int warp = threadIdx.x >> 5;
    const int lane = threadIdx.x & 31;
    const int row  = blockIdx.x * 4 + warp;  // b*N + n
    const int b    = row / N;
    const int n    = row % N;
    const int head = lane >> 3;
    const int sub  = lane & 7;

    // per-warp constant tables: [warp][head*8+p]
    __shared__ float sm_ox[4][32];
    __shared__ float sm_oy[4][32];
    __shared__ float sm_wp[4][32];

    // softmax over 8 points per head (8-lane segments)
    float l = __ldg(g_logits + row * 32 + lane);   // lane = head*8 + p
    float mx = l;
    #pragma unroll
    for (int o = 4; o > 0; o >>= 1) mx = fmaxf(mx, __shfl_xor_sync(FULL, mx, o, 8));
    float e = expf(l - mx);
    float ssum = e;
    #pragma unroll
    for (int o = 4; o > 0; o >>= 1) ssum += __shfl_xor_sync(FULL, ssum, o, 8);
    float aw = e / ssum;

    // offsets: lane holds pair for (head,p) = (lane>>3, lane&7)
    float2 oxy = __ldg((const float2*)(g_off + row * 64) + lane);

    // masks: lanes 0..5 probe camera s=lane; broadcast via ballot
    int sv = 0, hv = 0;
    unsigned occ = g_mask_occ;
    int st = (occ & 0x22u) ? 1 : ((occ & 0x1Cu) ? 4 : 8);
    if (lane < S) {
        int s = lane;
        long long e0 = ((long long)(s * B + 0) * N + n) * D;
        long long eb = ((long long)(s * B + b) * N + n) * D;
        #pragma unroll
        for (int d = 0; d < D; d++) {
            sv |= mask_nz(bev_mask, e0 + d, st);
            hv |= mask_nz(bev_mask, eb + d, st);
        }
    }
    unsigned selbits = __ballot_sync(FULL, (lane < S) && sv);
    unsigned hitbits = __ballot_sync(FULL, (lane < S) && hv);
    float inv_cnt = 1.0f / fmaxf((float)__popc(hitbits), 1.0f);

    // publish per-point constants (inv_cnt folded into weight)
    sm_ox[warp][lane] = oxy.x - 0.5f;
    sm_oy[warp][lane] = oxy.y - 0.5f;
    sm_wp[warp][lane] = aw * inv_cnt;
    __syncwarp();

    const float* oxp = &sm_ox[warp][head << 3];
    const float* oyp = &sm_oy[warp][head << 3];
    const float* wpp = &sm_wp[warp][head << 3];

    float4 acc = make_float4(0.f, 0.f, 0.f, 0.f);
    #pragma unroll
    for (int s = 0; s < S; s++) {
        if (!((selbits >> s) & 1u)) continue;  // warp-uniform
        const __half* vb = g_vproj + (size_t)((s * B + b) * M) * C + head * 32 + sub * 4;
        const float4* rp4 = (const float4*)(refpts + (((size_t)(s * B + b) * N + n) * D) * 2);
        float4 r0 = __ldg(rp4), r1 = __ldg(rp4 + 1);
        float xb[D] = {r0.x * Wf, r0.z * Wf, r1.x * Wf, r1.z * Wf};
        float yb[D] = {r0.y * Hf, r0.w * Hf, r1.y * Hf, r1.w * Hf};

        #pragma unroll
        for (int p = 0; p < NP; p++) {
            int dz = p & 3;          // p -> dz = p % D (reshape order)
            float x = xb[dz] + oxp[p];
            float y = yb[dz] + oyp[p];
            float xf = floorf(x), yf = floorf(y);
            float wx1 = x - xf, wy1 = y - yf;
            int x0 = (int)xf, y0 = (int)yf;

            uint2 u00, u01, u10, u11;
            // warp-uniform condition: no divergence
            if (((unsigned)x0 < (unsigned)(Wf - 1)) & ((unsigned)y0 < (unsigned)(Hf - 1))) {
                const uint2* base = (const uint2*)(vb + (y0 * Wf + x0) * C);
                u00 = __ldg(base);
                u01 = __ldg(base + (C / 4));               // +1 pixel
                u10 = __ldg(base + (Wf * C / 4));          // +1 row
                u11 = __ldg(base + ((Wf + 1) * C / 4));
            } else {
                u00 = fetchh(vb, y0,     x0);
                u01 = fetchh(vb, y0,     x0 + 1);
                u10 = fetchh(vb, y0 + 1, x0);
                u11 = fetchh(vb, y0 + 1, x0 + 1);
            }

            float wx0 = 1.0f - wx1, wy0 = 1.0f - wy1;
            __half2 hw00 = __float2half2_rn(wy0 * wx0);
            __half2 hw01 = __float2half2_rn(wy0 * wx1);
            __half2 hw10 = __float2half2_rn(wy1 * wx0);
            __half2 hw11 = __float2half2_rn(wy1 * wx1);

            __half2 sa = __hmul2(*(__half2*)&u00.x, hw00);
            sa = __hfma2(*(__half2*)&u01.x, hw01, sa);
            sa = __hfma2(*(__half2*)&u10.x, hw10, sa);
            sa = __hfma2(*(__half2*)&u11.x, hw11, sa);
            __half2 sb = __hmul2(*(__half2*)&u00.y, hw00);
            sb = __hfma2(*(__half2*)&u01.y, hw01, sb);
            sb = __hfma2(*(__half2*)&u10.y, hw10, sb);
            sb = __hfma2(*(__half2*)&u11.y, hw11, sb);

            float wgt = wpp[p];
            float2 fa = __half22float2(sa);
            float2 fb = __half22float2(sb);
            acc.x = fmaf(wgt, fa.x, acc.x);
            acc.y = fmaf(wgt, fa.y, acc.y);
            acc.z = fmaf(wgt, fb.x, acc.z);
            acc.w = fmaf(wgt, fb.y, acc.w);
        }
    }
    *(float4*)(g_slots + (size_t)row * C + lane * 4) = acc;
}

// ---------------------------------------------------------------------------
// Kernel 4: out = slots @ W_out + b_out + query. 32 rows/block, k-unroll x4.
// ---------------------------------------------------------------------------
__global__ void __launch_bounds__(128) k_out(
    const float* __restrict__ query,  // (B,N,C)
    const float* __restrict__ Wo,     // (C,C)
    const float* __restrict__ bo,     // (C,)
    float* __restrict__ out)          // (B,N,C)
{
    __shared__ float sv[32][C];
    const int t   = threadIdx.x;
    const int ro0 = blockIdx.x * 32;

    for (int idx = t; idx < 32 * 32; idx += 128) {
        int i  = idx >> 5;
        int c4 = (idx & 31) * 4;
        *(float4*)&sv[i][c4] = *(const float4*)(g_slots + (size_t)(ro0 + i) * C + c4);
    }
    __syncthreads();

    float acc[32];
    const float bias = __ldg(bo + t);
    #pragma unroll
    for (int r = 0; r < 32; r++) acc[r] = bias;

    for (int k = 0; k < C; k += 4) {
        float w0 = __ldg(Wo + (k + 0) * C + t);
        float w1 = __ldg(Wo + (k + 1) * C + t);
        float w2 = __ldg(Wo + (k + 2) * C + t);
        float w3 = __ldg(Wo + (k + 3) * C + t);
        #pragma unroll
        for (int r = 0; r < 32; r++) {
            float4 s4 = *(const float4*)&sv[r][k];
            acc[r] = fmaf(s4.x, w0, acc[r]);
            acc[r] = fmaf(s4.y, w1, acc[r]);
            acc[r] = fmaf(s4.z, w2, acc[r]);
            acc[r] = fmaf(s4.w, w3, acc[r]);
        }
    }
    #pragma unroll
    for (int r = 0; r < 32; r++) {
        size_t off = (size_t)(ro0 + r) * C + t;
        out[off] = acc[r] + query[off];
    }
}

// ---------------------------------------------------------------------------
// Launch. Input order: query, key, value, query_pos, reference_points_cam,
// bev_mask, spatial_shapes, W_value, b_value, W_offsets, b_offsets,
// W_attn, b_attn, W_out, b_out.
// ---------------------------------------------------------------------------
extern "C" void kernel_launch(void* const* d_in, const int* in_sizes, int n_in,
                              void* d_out, int out_size)
{
    const float* query = (const float*)d_in[0];
    // d_in[1] = key: unused by the reference math
    const float* value = (const float*)d_in[2];
    const float* qpos  = (const float*)d_in[3];
    const float* refp  = (const float*)d_in[4];
    const unsigned char* mask = (const unsigned char*)d_in[5];
    // d_in[6] = spatial_shapes (static, hardcoded H=32, W=88)
    const float* Wv   = (const float*)d_in[7];
    const float* bv   = (const float*)d_in[8];
    const float* Woff = (const float*)d_in[9];
    const float* boff = (const float*)d_in[10];
    const float* Wa   = (const float*)d_in[11];
    const float* ba   = (const float*)d_in[12];
    const float* Wo   = (const float*)d_in[13];
    const float* bo   = (const float*)d_in[14];
    float* out = (float*)d_out;

    k_detect<<<64, 256>>>((const uint4*)mask);
    k_vproj <<<(S * B * M) / 32, 128>>>(value, Wv, bv);
    k_qproj <<<(B * N) / 32,     128>>>(query, qpos, Woff, boff, Wa, ba);
    k_sample<<<(B * N) / 4,      128>>>(refp, mask);
    k_out   <<<(B * N) / 32,     128>>>(query, Wo, bo, out);
}

// round 10
// speedup vs baseline: 2.4551x; 1.0316x over previous
#include <cuda_runtime.h>
#include <cuda_fp16.h>

// Problem constants (static per reference)
constexpr int B  = 2;
constexpr int S  = 6;
constexpr int N  = 10000;
constexpr int C  = 128;
constexpr int D  = 4;
constexpr int NH = 4;     // heads
constexpr int NP = 8;     // points
constexpr int Hf = 32;
constexpr int Wf = 88;
constexpr int M  = Hf * Wf;   // 2816
constexpr int MASK_ELEMS = S * B * N * D;  // 480000
constexpr int NROWS = B * N;               // 20000

// Scratch (device globals; no allocation allowed)
__device__ __half   g_vproj [S * B * M * C];        // (s,b,m,c)  fp16
__device__ float    g_off   [B * N * NH * NP * 2];  // offsets (pixel units)
__device__ float    g_logits[B * N * NH * NP];      // attn logits
__device__ float    g_slots [B * N * C];            // masked-mean slots
__device__ unsigned g_mask_occ;                     // byte-position occupancy (OR-only: idempotent)

// packed fp32x2 FMA (Blackwell): d = a*b + d elementwise
__device__ __forceinline__ void ffma2(float2& d, float2 a, float2 b) {
    asm("fma.rn.f32x2 %0, %1, %2, %0;"
        : "+l"(reinterpret_cast<unsigned long long&>(d))
        : "l"(reinterpret_cast<unsigned long long&>(a)),
          "l"(reinterpret_cast<unsigned long long&>(b)));
}

// ---------------------------------------------------------------------------
// Kernel 0: bev_mask dtype probe (byte-position occupancy mod 8).
// atomicOr accumulation is idempotent -> deterministic across graph replays.
// ---------------------------------------------------------------------------
__global__ void k_detect(const uint4* __restrict__ mask16)
{
    unsigned occ = 0u;
    const int nvec = MASK_ELEMS / 16;  // 30000
    for (int i = blockIdx.x * blockDim.x + threadIdx.x; i < nvec; i += gridDim.x * blockDim.x) {
        uint4 v = __ldg(mask16 + i);
        unsigned w[4] = {v.x, v.y, v.z, v.w};
        #pragma unroll
        for (int wi = 0; wi < 4; wi++) {
            int base = (wi * 4) & 7;
            #pragma unroll
            for (int k = 0; k < 4; k++)
                if ((w[wi] >> (k * 8)) & 0xFFu) occ |= 1u << ((base + k) & 7);
        }
    }
    #pragma unroll
    for (int o = 16; o > 0; o >>= 1) occ |= __shfl_xor_sync(0xffffffffu, occ, o);
    if ((threadIdx.x & 31) == 0 && occ) atomicOr(&g_mask_occ, occ);
}

__device__ __forceinline__ int mask_nz(const unsigned char* __restrict__ mask,
                                       long long elem, int st)
{
    const unsigned char* p = mask + elem * st;
    int v = 0;
    for (int j = 0; j < st; j++) v |= p[j];
    return v != 0;
}

// ---------------------------------------------------------------------------
// Kernel 1: value projection. Register-tiled GEMM: 256 thr, 128-row tile,
// K in two 64-wide smem stages (pair-interleaved), f32x2 accumulators.
// Thread (tc,tm): cols tc*4..+3, row-pairs tm*8..+7 (16 rows). fp16 output.
// ---------------------------------------------------------------------------
__global__ void __launch_bounds__(256) k_vproj(
    const float* __restrict__ value,  // (S,M,B,C)
    const float* __restrict__ Wv,     // (C,C)
    const float* __restrict__ bv)     // (C,)
{
    __shared__ float svp[64][64][2];  // [rowpair][k-in-tile][parity]  32KB
    const int t   = threadIdx.x;
    const int ro0 = blockIdx.x * 128;
    const int tc  = t & 31;
    const int tm  = t >> 5;

    float2 acc[8][4];
    {
        float4 b4 = __ldg((const float4*)(bv + tc * 4));
        #pragma unroll
        for (int i = 0; i < 8; i++) {
            acc[i][0] = make_float2(b4.x, b4.x);
            acc[i][1] = make_float2(b4.y, b4.y);
            acc[i][2] = make_float2(b4.z, b4.z);
            acc[i][3] = make_float2(b4.w, b4.w);
        }
    }

    for (int kt = 0; kt < 2; kt++) {
        if (kt) __syncthreads();
        // stage 128 rows x 64 k (pair-interleaved)
        for (int idx = t; idx < 128 * 16; idx += 256) {
            int r  = idx >> 4;
            int k4 = (idx & 15) * 4;
            int ro = ro0 + r;
            int sb = ro / M, m = ro % M;
            int s  = sb / B, bb = sb % B;
            float4 v4 = *(const float4*)(value + ((size_t)((s * M + m) * B + bb) * C + kt * 64 + k4));
            svp[r >> 1][k4 + 0][r & 1] = v4.x;
            svp[r >> 1][k4 + 1][r & 1] = v4.y;
            svp[r >> 1][k4 + 2][r & 1] = v4.z;
            svp[r >> 1][k4 + 3][r & 1] = v4.w;
        }
        __syncthreads();

        const float* Wk = Wv + (size_t)(kt * 64) * C + tc * 4;
        #pragma unroll 2
        for (int k = 0; k < 64; k += 2) {
            float4 wa = __ldg((const float4*)(Wk + (size_t)k * C));
            float4 wb = __ldg((const float4*)(Wk + (size_t)(k + 1) * C));
            float2 wpa0 = make_float2(wa.x, wa.x), wpa1 = make_float2(wa.y, wa.y);
            float2 wpa2 = make_float2(wa.z, wa.z), wpa3 = make_float2(wa.w, wa.w);
            float2 wpb0 = make_float2(wb.x, wb.x), wpb1 = make_float2(wb.y, wb.y);
            float2 wpb2 = make_float2(wb.z, wb.z), wpb3 = make_float2(wb.w, wb.w);
            #pragma unroll
            for (int i = 0; i < 8; i++) {
                float4 a4 = *(const float4*)&svp[tm * 8 + i][k][0];   // broadcast
                float2 ak0 = make_float2(a4.x, a4.y);  // k,   rows (even,odd)
                float2 ak1 = make_float2(a4.z, a4.w);  // k+1
                ffma2(acc[i][0], ak0, wpa0); ffma2(acc[i][0], ak1, wpb0);
                ffma2(acc[i][1], ak0, wpa1); ffma2(acc[i][1], ak1, wpb1);
                ffma2(acc[i][2], ak0, wpa2); ffma2(acc[i][2], ak1, wpb2);
                ffma2(acc[i][3], ak0, wpa3); ffma2(acc[i][3], ak1, wpb3);
            }
        }
    }

    #pragma unroll
    for (int i = 0; i < 8; i++) {
        int r0 = ro0 + (tm * 8 + i) * 2;
        __half2 e01 = __floats2half2_rn(acc[i][0].x, acc[i][1].x);
        __half2 e23 = __floats2half2_rn(acc[i][2].x, acc[i][3].x);
        __half2 o01 = __floats2half2_rn(acc[i][0].y, acc[i][1].y);
        __half2 o23 = __floats2half2_rn(acc[i][2].y, acc[i][3].y);
        uint2 ue, uo;
        ue.x = *(unsigned*)&e01; ue.y = *(unsigned*)&e23;
        uo.x = *(unsigned*)&o01; uo.y = *(unsigned*)&o23;
        *(uint2*)&g_vproj[(size_t)r0 * C + tc * 4]       = ue;
        *(uint2*)&g_vproj[(size_t)(r0 + 1) * C + tc * 4] = uo;
    }
}

// ---------------------------------------------------------------------------
// Kernel 2: q = query+query_pos; offsets = q@W_off+b ; logits = q@W_a+b.
// Same register-tiled skeleton; 96 output cols -> col groups tc<24 active.
// Rows guarded (NROWS=20000 not a multiple of 128).
// ---------------------------------------------------------------------------
__global__ void __launch_bounds__(256) k_qproj(
    const float* __restrict__ query,  // (B,N,C)
    const float* __restrict__ qpos,   // (B,N,C)
    const float* __restrict__ Woff,   // (C,64)
    const float* __restrict__ boff,   // (64,)
    const float* __restrict__ Wa,     // (C,32)
    const float* __restrict__ ba)     // (32,)
{
    __shared__ float svp[64][64][2];
    const int t   = threadIdx.x;
    const int ro0 = blockIdx.x * 128;
    const int tc  = t & 31;           // active if tc < 24
    const int tm  = t >> 5;
    const int c   = tc * 4;
    const bool act = (tc < 24);

    float2 acc[8][4];
    if (act) {
        float4 b4;
        if (c < 64) b4 = *(const float4*)(boff + c);
        else        b4 = *(const float4*)(ba + (c - 64));
        #pragma unroll
        for (int i = 0; i < 8; i++) {
            acc[i][0] = make_float2(b4.x, b4.x);
            acc[i][1] = make_float2(b4.y, b4.y);
            acc[i][2] = make_float2(b4.z, b4.z);
            acc[i][3] = make_float2(b4.w, b4.w);
        }
    }

    for (int kt = 0; kt < 2; kt++) {
        if (kt) __syncthreads();
        for (int idx = t; idx < 128 * 16; idx += 256) {
            int r  = idx >> 4;
            int k4 = (idx & 15) * 4;
            int ro = min(ro0 + r, NROWS - 1);  // clamp (dup rows OK, stores guarded)
            size_t off = (size_t)ro * C + kt * 64 + k4;
            float4 a = *(const float4*)(query + off);
            float4 p = *(const float4*)(qpos + off);
            svp[r >> 1][k4 + 0][r & 1] = a.x + p.x;
            svp[r >> 1][k4 + 1][r & 1] = a.y + p.y;
            svp[r >> 1][k4 + 2][r & 1] = a.z + p.z;
            svp[r >> 1][k4 + 3][r & 1] = a.w + p.w;
        }
        __syncthreads();

        if (act) {
            const float* Wk;
            int wstride;
            if (c < 64) { Wk = Woff + (size_t)(kt * 64) * 64 + c;        wstride = 64; }
            else        { Wk = Wa  + (size_t)(kt * 64) * 32 + (c - 64);  wstride = 32; }
            #pragma unroll 2
            for (int k = 0; k < 64; k += 2) {
                float4 wa4 = *(const float4*)(Wk + (size_t)k * wstride);
                float4 wb4 = *(const float4*)(Wk + (size_t)(k + 1) * wstride);
                float2 wpa0 = make_float2(wa4.x, wa4.x), wpa1 = make_float2(wa4.y, wa4.y);
                float2 wpa2 = make_float2(wa4.z, wa4.z), wpa3 = make_float2(wa4.w, wa4.w);
                float2 wpb0 = make_float2(wb4.x, wb4.x), wpb1 = make_float2(wb4.y, wb4.y);
                float2 wpb2 = make_float2(wb4.z, wb4.z), wpb3 = make_float2(wb4.w, wb4.w);
                #pragma unroll
                for (int i = 0; i < 8; i++) {
                    float4 a4 = *(const float4*)&svp[tm * 8 + i][k][0];
                    float2 ak0 = make_float2(a4.x, a4.y);
                    float2 ak1 = make_float2(a4.z, a4.w);
                    ffma2(acc[i][0], ak0, wpa0); ffma2(acc[i][0], ak1, wpb0);
                    ffma2(acc[i][1], ak0, wpa1); ffma2(acc[i][1], ak1, wpb1);
                    ffma2(acc[i][2], ak0, wpa2); ffma2(acc[i][2], ak1, wpb2);
                    ffma2(acc[i][3], ak0, wpa3); ffma2(acc[i][3], ak1, wpb3);
                }
            }
        }
    }

    if (act) {
        #pragma unroll
        for (int i = 0; i < 8; i++) {
            int r0 = ro0 + (tm * 8 + i) * 2;
            #pragma unroll
            for (int par = 0; par < 2; par++) {
                int row = r0 + par;
                if (row >= NROWS) continue;
                float4 v;
                if (par == 0) v = make_float4(acc[i][0].x, acc[i][1].x, acc[i][2].x, acc[i][3].x);
                else          v = make_float4(acc[i][0].y, acc[i][1].y, acc[i][2].y, acc[i][3].y);
                if (c < 64) *(float4*)(g_off    + (size_t)row * 64 + c)        = v;
                else        *(float4*)(g_logits + (size_t)row * 32 + (c - 64)) = v;
            }
        }
    }
}

// ---------------------------------------------------------------------------
// Kernel 3: bilinear deformable sampling, ONE WARP PER QUERY, fp16 values.
// (unchanged from R9 passing version)
// ---------------------------------------------------------------------------
__device__ __forceinline__ uint2 fetchh(const __half* __restrict__ vb, int yi, int xi) {
    bool valid = ((unsigned)yi < (unsigned)Hf) && ((unsigned)xi < (unsigned)Wf);
    int yc = min(max(yi, 0), Hf - 1);
    int xc = min(max(xi, 0), Wf - 1);
    uint2 v = __ldg((const uint2*)(vb + (yc * Wf + xc) * C));
    if (!valid) v = make_uint2(0u, 0u);
    return v;
}

__global__ void __launch_bounds__(128, 10) k_sample(
    const float* __restrict__ refpts,           // (S,B,N,D,2)
    const unsigned char* __restrict__ bev_mask) // (S,B,N,D), stride detected
{
    const unsigned FULL = 0xffffffffu;
    const int warp = threadIdx.x >> 5;
    const int lane = threadIdx.x & 31;
    const int row  = blockIdx.x * 4 + warp;  // b*N + n
    const int b    = row / N;
    const int n    = row % N;
    const int head = lane >> 3;
    const int sub  = lane & 7;

    __shared__ float sm_ox[4][32];
    __shared__ float sm_oy[4][32];
    __shared__ float sm_wp[4][32];

    float l = __ldg(g_logits + row * 32 + lane);   // lane = head*8 + p
    float mx = l;
    #pragma unroll
    for (int o = 4; o > 0; o >>= 1) mx = fmaxf(mx, __shfl_xor_sync(FULL, mx, o, 8));
    float e = expf(l - mx);
    float ssum = e;
    #pragma unroll
    for (int o = 4; o > 0; o >>= 1) ssum += __shfl_xor_sync(FULL, ssum, o, 8);
    float aw = e / ssum;

    float2 oxy = __ldg((const float2*)(g_off + row * 64) + lane);

    int sv = 0, hv = 0;
    unsigned occ = g_mask_occ;
    int st = (occ & 0x22u) ? 1 : ((occ & 0x1Cu) ? 4 : 8);
    if (lane < S) {
        int s = lane;
        long long e0 = ((long long)(s * B + 0) * N + n) * D;
        long long eb = ((long long)(s * B + b) * N + n) * D;
        #pragma unroll
        for (int d = 0; d < D; d++) {
            sv |= mask_nz(bev_mask, e0 + d, st);
            hv |= mask_nz(bev_mask, eb + d, st);
        }
    }
    unsigned selbits = __ballot_sync(FULL, (lane < S) && sv);
    unsigned hitbits = __ballot_sync(FULL, (lane < S) && hv);
    float inv_cnt = 1.0f / fmaxf((float)__popc(hitbits), 1.0f);

    sm_ox[warp][lane] = oxy.x - 0.5f;
    sm_oy[warp][lane] = oxy.y - 0.5f;
    sm_wp[warp][lane] = aw * inv_cnt;
    __syncwarp();

    const float* oxp = &sm_ox[warp][head << 3];
    const float* oyp = &sm_oy[warp][head << 3];
    const float* wpp = &sm_wp[warp][head << 3];

    float4 acc = make_float4(0.f, 0.f, 0.f, 0.f);
    #pragma unroll
    for (int s = 0; s < S; s++) {
        if (!((selbits >> s) & 1u)) continue;  // warp-uniform
        const __half* vb = g_vproj + (size_t)((s * B + b) * M) * C + head * 32 + sub * 4;
        const float4* rp4 = (const float4*)(refpts + (((size_t)(s * B + b) * N + n) * D) * 2);
        float4 r0 = __ldg(rp4), r1 = __ldg(rp4 + 1);
        float xb[D] = {r0.x * Wf, r0.z * Wf, r1.x * Wf, r1.z * Wf};
        float yb[D] = {r0.y * Hf, r0.w * Hf, r1.y * Hf, r1.w * Hf};

        #pragma unroll
        for (int p = 0; p < NP; p++) {
            int dz = p & 3;
            float x = xb[dz] + oxp[p];
            float y = yb[dz] + oyp[p];
            float xf = floorf(x), yf = floorf(y);
            float wx1 = x - xf, wy1 = y - yf;
            int x0 = (int)xf, y0 = (int)yf;

            uint2 u00, u01, u10, u11;
            if (((unsigned)x0 < (unsigned)(Wf - 1)) & ((unsigned)y0 < (unsigned)(Hf - 1))) {
                const uint2* base = (const uint2*)(vb + (y0 * Wf + x0) * C);
                u00 = __ldg(base);
                u01 = __ldg(base + (C / 4));
                u10 = __ldg(base + (Wf * C / 4));
                u11 = __ldg(base + ((Wf + 1) * C / 4));
            } else {
                u00 = fetchh(vb, y0,     x0);
                u01 = fetchh(vb, y0,     x0 + 1);
                u10 = fetchh(vb, y0 + 1, x0);
                u11 = fetchh(vb, y0 + 1, x0 + 1);
            }

            float wx0 = 1.0f - wx1, wy0 = 1.0f - wy1;
            __half2 hw00 = __float2half2_rn(wy0 * wx0);
            __half2 hw01 = __float2half2_rn(wy0 * wx1);
            __half2 hw10 = __float2half2_rn(wy1 * wx0);
            __half2 hw11 = __float2half2_rn(wy1 * wx1);

            __half2 sa = __hmul2(*(__half2*)&u00.x, hw00);
            sa = __hfma2(*(__half2*)&u01.x, hw01, sa);
            sa = __hfma2(*(__half2*)&u10.x, hw10, sa);
            sa = __hfma2(*(__half2*)&u11.x, hw11, sa);
            __half2 sb = __hmul2(*(__half2*)&u00.y, hw00);
            sb = __hfma2(*(__half2*)&u01.y, hw01, sb);
            sb = __hfma2(*(__half2*)&u10.y, hw10, sb);
            sb = __hfma2(*(__half2*)&u11.y, hw11, sb);

            float wgt = wpp[p];
            float2 fa = __half22float2(sa);
            float2 fb = __half22float2(sb);
            acc.x = fmaf(wgt, fa.x, acc.x);
            acc.y = fmaf(wgt, fa.y, acc.y);
            acc.z = fmaf(wgt, fb.x, acc.z);
            acc.w = fmaf(wgt, fb.y, acc.w);
        }
    }
    *(float4*)(g_slots + (size_t)row * C + lane * 4) = acc;
}

// ---------------------------------------------------------------------------
// Kernel 4: out = slots @ W_out + b_out + query. Register-tiled, rows guarded.
// ---------------------------------------------------------------------------
__global__ void __launch_bounds__(256) k_out(
    const float* __restrict__ query,  // (B,N,C)
    const float* __restrict__ Wo,     // (C,C)
    const float* __restrict__ bo,     // (C,)
    float* __restrict__ out)          // (B,N,C)
{
    __shared__ float svp[64][64][2];
    const int t   = threadIdx.x;
    const int ro0 = blockIdx.x * 128;
    const int tc  = t & 31;
    const int tm  = t >> 5;

    float2 acc[8][4];
    {
        float4 b4 = __ldg((const float4*)(bo + tc * 4));
        #pragma unroll
        for (int i = 0; i < 8; i++) {
            acc[i][0] = make_float2(b4.x, b4.x);
            acc[i][1] = make_float2(b4.y, b4.y);
            acc[i][2] = make_float2(b4.z, b4.z);
            acc[i][3] = make_float2(b4.w, b4.w);
        }
    }

    for (int kt = 0; kt < 2; kt++) {
        if (kt) __syncthreads();
        for (int idx = t; idx < 128 * 16; idx += 256) {
            int r  = idx >> 4;
            int k4 = (idx & 15) * 4;
            int ro = min(ro0 + r, NROWS - 1);
            float4 v4 = *(const float4*)(g_slots + (size_t)ro * C + kt * 64 + k4);
            svp[r >> 1][k4 + 0][r & 1] = v4.x;
            svp[r >> 1][k4 + 1][r & 1] = v4.y;
            svp[r >> 1][k4 + 2][r & 1] = v4.z;
            svp[r >> 1][k4 + 3][r & 1] = v4.w;
        }
        __syncthreads();

        const float* Wk = Wo + (size_t)(kt * 64) * C + tc * 4;
        #pragma unroll 2
        for (int k = 0; k < 64; k += 2) {
            float4 wa = __ldg((const float4*)(Wk + (size_t)k * C));
            float4 wb = __ldg((const float4*)(Wk + (size_t)(k + 1) * C));
            float2 wpa0 = make_float2(wa.x, wa.x), wpa1 = make_float2(wa.y, wa.y);
            float2 wpa2 = make_float2(wa.z, wa.z), wpa3 = make_float2(wa.w, wa.w);
            float2 wpb0 = make_float2(wb.x, wb.x), wpb1 = make_float2(wb.y, wb.y);
            float2 wpb2 = make_float2(wb.z, wb.z), wpb3 = make_float2(wb.w, wb.w);
            #pragma unroll
            for (int i = 0; i < 8; i++) {
                float4 a4 = *(const float4*)&svp[tm * 8 + i][k][0];
                float2 ak0 = make_float2(a4.x, a4.y);
                float2 ak1 = make_float2(a4.z, a4.w);
                ffma2(acc[i][0], ak0, wpa0); ffma2(acc[i][0], ak1, wpb0);
                ffma2(acc[i][1], ak0, wpa1); ffma2(acc[i][1], ak1, wpb1);
                ffma2(acc[i][2], ak0, wpa2); ffma2(acc[i][2], ak1, wpb2);
                ffma2(acc[i][3], ak0, wpa3); ffma2(acc[i][3], ak1, wpb3);
            }
        }
    }

    #pragma unroll
    for (int i = 0; i < 8; i++) {
        int r0 = ro0 + (tm * 8 + i) * 2;
        #pragma unroll
        for (int par = 0; par < 2; par++) {
            int row = r0 + par;
            if (row >= NROWS) continue;
            size_t off = (size_t)row * C + tc * 4;
            float4 q4 = *(const float4*)(query + off);
            float4 v;
            if (par == 0) v = make_float4(acc[i][0].x + q4.x, acc[i][1].x + q4.y,
                                          acc[i][2].x + q4.z, acc[i][3].x + q4.w);
            else          v = make_float4(acc[i][0].y + q4.x, acc[i][1].y + q4.y,
                                          acc[i][2].y + q4.z, acc[i][3].y + q4.w);
            *(float4*)(out + off) = v;
        }
    }
}

// ---------------------------------------------------------------------------
// Launch. Input order: query, key, value, query_pos, reference_points_cam,
// bev_mask, spatial_shapes, W_value, b_value, W_offsets, b_offsets,
// W_attn, b_attn, W_out, b_out.
// ---------------------------------------------------------------------------
extern "C" void kernel_launch(void* const* d_in, const int* in_sizes, int n_in,
                              void* d_out, int out_size)
{
    const float* query = (const float*)d_in[0];
    // d_in[1] = key: unused by the reference math
    const float* value = (const float*)d_in[2];
    const float* qpos  = (const float*)d_in[3];
    const float* refp  = (const float*)d_in[4];
    const unsigned char* mask = (const unsigned char*)d_in[5];
    // d_in[6] = spatial_shapes (static, hardcoded H=32, W=88)
    const float* Wv   = (const float*)d_in[7];
    const float* bv   = (const float*)d_in[8];
    const float* Woff = (const float*)d_in[9];
    const float* boff = (const float*)d_in[10];
    const float* Wa   = (const float*)d_in[11];
    const float* ba   = (const float*)d_in[12];
    const float* Wo   = (const float*)d_in[13];
    const float* bo   = (const float*)d_in[14];
    float* out = (float*)d_out;

    k_detect<<<64, 256>>>((const uint4*)mask);
    k_vproj <<<(S * B * M) / 128, 256>>>(value, Wv, bv);
    k_qproj <<<(NROWS + 127) / 128, 256>>>(query, qpos, Woff, boff, Wa, ba);
    k_sample<<<NROWS / 4, 128>>>(refp, mask);
    k_out   <<<(NROWS + 127) / 128, 256>>>(query, Wo, bo, out);
}

// round 11
// speedup vs baseline: 2.7249x; 1.1099x over previous
#include <cuda_runtime.h>
#include <cuda_fp16.h>

// Problem constants (static per reference)
constexpr int B  = 2;
constexpr int S  = 6;
constexpr int N  = 10000;
constexpr int C  = 128;
constexpr int D  = 4;
constexpr int NH = 4;     // heads
constexpr int NP = 8;     // points
constexpr int Hf = 32;
constexpr int Wf = 88;
constexpr int M  = Hf * Wf;        // 2816
constexpr int WP = Wf + 4;         // 92  (2-px pad each side)
constexpr int HP = Hf + 4;         // 36
constexpr int MP = HP * WP;        // 3312 padded pixels
constexpr int RING = MP - M;       // 496 pad cells per (s,b)
constexpr int MASK_ELEMS = S * B * N * D;  // 480000
constexpr int NROWS = B * N;               // 20000

// Scratch (device globals; no allocation allowed)
__device__ __half   g_vproj [S * B * MP * C];       // padded (s,b,py,px,c) fp16
__device__ float    g_off   [B * N * NH * NP * 2];  // offsets (pixel units)
__device__ float    g_logits[B * N * NH * NP];      // attn logits
__device__ float    g_slots [B * N * C];            // masked-mean slots
__device__ unsigned g_mask_occ;                     // byte-position occupancy

// packed fp32x2 FMA (Blackwell): d = a*b + d elementwise
__device__ __forceinline__ void ffma2(float2& d, float2 a, float2 b) {
    asm("fma.rn.f32x2 %0, %1, %2, %0;"
        : "+l"(reinterpret_cast<unsigned long long&>(d))
        : "l"(reinterpret_cast<unsigned long long&>(a)),
          "l"(reinterpret_cast<unsigned long long&>(b)));
}

// ---------------------------------------------------------------------------
// Kernel 0: bev_mask dtype probe (byte-position occupancy mod 8).
// ---------------------------------------------------------------------------
__global__ void k_detect(const uint4* __restrict__ mask16)
{
    unsigned occ = 0u;
    const int nvec = MASK_ELEMS / 16;
    for (int i = blockIdx.x * blockDim.x + threadIdx.x; i < nvec; i += gridDim.x * blockDim.x) {
        uint4 v = __ldg(mask16 + i);
        unsigned w[4] = {v.x, v.y, v.z, v.w};
        #pragma unroll
        for (int wi = 0; wi < 4; wi++) {
            int base = (wi * 4) & 7;
            #pragma unroll
            for (int k = 0; k < 4; k++)
                if ((w[wi] >> (k * 8)) & 0xFFu) occ |= 1u << ((base + k) & 7);
        }
    }
    #pragma unroll
    for (int o = 16; o > 0; o >>= 1) occ |= __shfl_xor_sync(0xffffffffu, occ, o);
    if ((threadIdx.x & 31) == 0 && occ) atomicOr(&g_mask_occ, occ);
}

__device__ __forceinline__ int mask_nz(const unsigned char* __restrict__ mask,
                                       long long elem, int st)
{
    const unsigned char* p = mask + elem * st;
    int v = 0;
    for (int j = 0; j < st; j++) v |= p[j];
    return v != 0;
}

// ---------------------------------------------------------------------------
// Kernel 0b: zero the pad ring of g_vproj (every launch; idempotent).
// Ring cells per (s,b): rows py in {0,1,34,35} full width + cols px in
// {0,1,90,91} for py 2..33.  Each cell = 128 halves = 16 uint4 chunks.
// ---------------------------------------------------------------------------
__global__ void k_zerofill()
{
    const int total = S * B * RING * 16;   // 95232 uint4 stores
    for (int idx = blockIdx.x * blockDim.x + threadIdx.x; idx < total; idx += gridDim.x * blockDim.x) {
        int chunk = idx & 15;
        int cellI = idx >> 4;
        int sb = cellI / RING;
        int c  = cellI % RING;
        int py, px;
        if (c < 4 * WP) {                   // rows 0,1,34,35 (full width)
            int rr = c / WP;                // 0..3
            py = (rr < 2) ? rr : rr + 32;   // 0,1,34,35
            px = c % WP;
        } else {
            int c2 = c - 4 * WP;
            py = 2 + (c2 >> 2);             // 2..33
            int e = c2 & 3;                 // 0..3 -> 0,1,90,91
            px = (e < 2) ? e : e + 88;
        }
        size_t base = ((size_t)sb * MP + py * WP + px) * C + chunk * 8;
        *(uint4*)&g_vproj[base] = make_uint4(0u, 0u, 0u, 0u);
    }
}

// ---------------------------------------------------------------------------
// Kernel 1: value projection. Register-tiled GEMM, 64-row tiles, 256 thr.
// Thread (tc,tm): cols tc*4..+3, row-pairs tm*4..+3 (8 rows). Writes fp16
// into the PADDED canvas.
// ---------------------------------------------------------------------------
__global__ void __launch_bounds__(256) k_vproj(
    const float* __restrict__ value,  // (S,M,B,C)
    const float* __restrict__ Wv,     // (C,C)
    const float* __restrict__ bv)     // (C,)
{
    __shared__ float svp[32][64][2];  // [rowpair][k-in-tile][parity] 16KB
    const int t   = threadIdx.x;
    const int ro0 = blockIdx.x * 64;
    const int tc  = t & 31;
    const int tm  = t >> 5;

    float2 acc[4][4];
    {
        float4 b4 = __ldg((const float4*)(bv + tc * 4));
        #pragma unroll
        for (int i = 0; i < 4; i++) {
            acc[i][0] = make_float2(b4.x, b4.x);
            acc[i][1] = make_float2(b4.y, b4.y);
            acc[i][2] = make_float2(b4.z, b4.z);
            acc[i][3] = make_float2(b4.w, b4.w);
        }
    }

    for (int kt = 0; kt < 2; kt++) {
        if (kt) __syncthreads();
        for (int idx = t; idx < 64 * 16; idx += 256) {
            int r  = idx >> 4;
            int k4 = (idx & 15) * 4;
            int ro = ro0 + r;
            int sb = ro / M, m = ro % M;
            int s  = sb / B, bb = sb % B;
            float4 v4 = *(const float4*)(value + ((size_t)((s * M + m) * B + bb) * C + kt * 64 + k4));
            svp[r >> 1][k4 + 0][r & 1] = v4.x;
            svp[r >> 1][k4 + 1][r & 1] = v4.y;
            svp[r >> 1][k4 + 2][r & 1] = v4.z;
            svp[r >> 1][k4 + 3][r & 1] = v4.w;
        }
        __syncthreads();

        const float* Wk = Wv + (size_t)(kt * 64) * C + tc * 4;
        #pragma unroll 2
        for (int k = 0; k < 64; k += 2) {
            float4 wa = __ldg((const float4*)(Wk + (size_t)k * C));
            float4 wb = __ldg((const float4*)(Wk + (size_t)(k + 1) * C));
            float2 wpa0 = make_float2(wa.x, wa.x), wpa1 = make_float2(wa.y, wa.y);
            float2 wpa2 = make_float2(wa.z, wa.z), wpa3 = make_float2(wa.w, wa.w);
            float2 wpb0 = make_float2(wb.x, wb.x), wpb1 = make_float2(wb.y, wb.y);
            float2 wpb2 = make_float2(wb.z, wb.z), wpb3 = make_float2(wb.w, wb.w);
            #pragma unroll
            for (int i = 0; i < 4; i++) {
                float4 a4 = *(const float4*)&svp[tm * 4 + i][k][0];
                float2 ak0 = make_float2(a4.x, a4.y);
                float2 ak1 = make_float2(a4.z, a4.w);
                ffma2(acc[i][0], ak0, wpa0); ffma2(acc[i][0], ak1, wpb0);
                ffma2(acc[i][1], ak0, wpa1); ffma2(acc[i][1], ak1, wpb1);
                ffma2(acc[i][2], ak0, wpa2); ffma2(acc[i][2], ak1, wpb2);
                ffma2(acc[i][3], ak0, wpa3); ffma2(acc[i][3], ak1, wpb3);
            }
        }
    }

    #pragma unroll
    for (int i = 0; i < 4; i++) {
        int r0 = ro0 + (tm * 4 + i) * 2;
        #pragma unroll
        for (int par = 0; par < 2; par++) {
            int ro = r0 + par;
            int sb = ro / M, m = ro % M;
            int y = m / Wf, x = m % Wf;
            size_t pm = (size_t)sb * MP + (y + 2) * WP + (x + 2);
            __half2 h01, h23;
            if (par == 0) {
                h01 = __floats2half2_rn(acc[i][0].x, acc[i][1].x);
                h23 = __floats2half2_rn(acc[i][2].x, acc[i][3].x);
            } else {
                h01 = __floats2half2_rn(acc[i][0].y, acc[i][1].y);
                h23 = __floats2half2_rn(acc[i][2].y, acc[i][3].y);
            }
            uint2 u; u.x = *(unsigned*)&h01; u.y = *(unsigned*)&h23;
            *(uint2*)&g_vproj[pm * C + tc * 4] = u;
        }
    }
}

// ---------------------------------------------------------------------------
// Kernel 2: q = query+query_pos; offsets = q@W_off+b ; logits = q@W_a+b.
// 64-row tiles; 96 output cols -> tc<24 active; rows guarded.
// ---------------------------------------------------------------------------
__global__ void __launch_bounds__(256) k_qproj(
    const float* __restrict__ query,  // (B,N,C)
    const float* __restrict__ qpos,   // (B,N,C)
    const float* __restrict__ Woff,   // (C,64)
    const float* __restrict__ boff,   // (64,)
    const float* __restrict__ Wa,     // (C,32)
    const float* __restrict__ ba)     // (32,)
{
    __shared__ float svp[32][64][2];
    const int t   = threadIdx.x;
    const int ro0 = blockIdx.x * 64;
    const int tc  = t & 31;
    const int tm  = t >> 5;
    const int c   = tc * 4;
    const bool act = (tc < 24);

    float2 acc[4][4];
    if (act) {
        float4 b4;
        if (c < 64) b4 = *(const float4*)(boff + c);
        else        b4 = *(const float4*)(ba + (c - 64));
        #pragma unroll
        for (int i = 0; i < 4; i++) {
            acc[i][0] = make_float2(b4.x, b4.x);
            acc[i][1] = make_float2(b4.y, b4.y);
            acc[i][2] = make_float2(b4.z, b4.z);
            acc[i][3] = make_float2(b4.w, b4.w);
        }
    }

    for (int kt = 0; kt < 2; kt++) {
        if (kt) __syncthreads();
        for (int idx = t; idx < 64 * 16; idx += 256) {
            int r  = idx >> 4;
            int k4 = (idx & 15) * 4;
            int ro = min(ro0 + r, NROWS - 1);
            size_t off = (size_t)ro * C + kt * 64 + k4;
            float4 a = *(const float4*)(query + off);
            float4 p = *(const float4*)(qpos + off);
            svp[r >> 1][k4 + 0][r & 1] = a.x + p.x;
            svp[r >> 1][k4 + 1][r & 1] = a.y + p.y;
            svp[r >> 1][k4 + 2][r & 1] = a.z + p.z;
            svp[r >> 1][k4 + 3][r & 1] = a.w + p.w;
        }
        __syncthreads();

        if (act) {
            const float* Wk;
            int wstride;
            if (c < 64) { Wk = Woff + (size_t)(kt * 64) * 64 + c;        wstride = 64; }
            else        { Wk = Wa  + (size_t)(kt * 64) * 32 + (c - 64);  wstride = 32; }
            #pragma unroll 2
            for (int k = 0; k < 64; k += 2) {
                float4 wa4 = *(const float4*)(Wk + (size_t)k * wstride);
                float4 wb4 = *(const float4*)(Wk + (size_t)(k + 1) * wstride);
                float2 wpa0 = make_float2(wa4.x, wa4.x), wpa1 = make_float2(wa4.y, wa4.y);
                float2 wpa2 = make_float2(wa4.z, wa4.z), wpa3 = make_float2(wa4.w, wa4.w);
                float2 wpb0 = make_float2(wb4.x, wb4.x), wpb1 = make_float2(wb4.y, wb4.y);
                float2 wpb2 = make_float2(wb4.z, wb4.z), wpb3 = make_float2(wb4.w, wb4.w);
                #pragma unroll
                for (int i = 0; i < 4; i++) {
                    float4 a4 = *(const float4*)&svp[tm * 4 + i][k][0];
                    float2 ak0 = make_float2(a4.x, a4.y);
                    float2 ak1 = make_float2(a4.z, a4.w);
                    ffma2(acc[i][0], ak0, wpa0); ffma2(acc[i][0], ak1, wpb0);
                    ffma2(acc[i][1], ak0, wpa1); ffma2(acc[i][1], ak1, wpb1);
                    ffma2(acc[i][2], ak0, wpa2); ffma2(acc[i][2], ak1, wpb2);
                    ffma2(acc[i][3], ak0, wpa3); ffma2(acc[i][3], ak1, wpb3);
                }
            }
        }
    }

    if (act) {
        #pragma unroll
        for (int i = 0; i < 4; i++) {
            int r0 = ro0 + (tm * 4 + i) * 2;
            #pragma unroll
            for (int par = 0; par < 2; par++) {
                int row = r0 + par;
                if (row >= NROWS) continue;
                float4 v;
                if (par == 0) v = make_float4(acc[i][0].x, acc[i][1].x, acc[i][2].x, acc[i][3].x);
                else          v = make_float4(acc[i][0].y, acc[i][1].y, acc[i][2].y, acc[i][3].y);
                if (c < 64) *(float4*)(g_off    + (size_t)row * 64 + c)        = v;
                else        *(float4*)(g_logits + (size_t)row * 32 + (c - 64)) = v;
            }
        }
    }
}

// ---------------------------------------------------------------------------
// Kernel 3: bilinear deformable sampling, ONE WARP PER QUERY, fp16 padded
// canvas. BRANCHLESS: clamp into the zero ring reproduces grid_sample
// zero-padding exactly for all coordinates.
// ---------------------------------------------------------------------------
__global__ void __launch_bounds__(128, 10) k_sample(
    const float* __restrict__ refpts,           // (S,B,N,D,2)
    const unsigned char* __restrict__ bev_mask) // (S,B,N,D), stride detected
{
    const unsigned FULL = 0xffffffffu;
    const int warp = threadIdx.x >> 5;
    const int lane = threadIdx.x & 31;
    const int row  = blockIdx.x * 4 + warp;  // b*N + n
    const int b    = row / N;
    const int n    = row % N;
    const int head = lane >> 3;
    const int sub  = lane & 7;

    __shared__ float sm_ox[4][32];
    __shared__ float sm_oy[4][32];
    __shared__ float sm_wp[4][32];

    float l = __ldg(g_logits + row * 32 + lane);   // lane = head*8 + p
    float mx = l;
    #pragma unroll
    for (int o = 4; o > 0; o >>= 1) mx = fmaxf(mx, __shfl_xor_sync(FULL, mx, o, 8));
    float e = expf(l - mx);
    float ssum = e;
    #pragma unroll
    for (int o = 4; o > 0; o >>= 1) ssum += __shfl_xor_sync(FULL, ssum, o, 8);
    float aw = e / ssum;

    float2 oxy = __ldg((const float2*)(g_off + row * 64) + lane);

    int sv = 0, hv = 0;
    unsigned occ = g_mask_occ;
    int st = (occ & 0x22u) ? 1 : ((occ & 0x1Cu) ? 4 : 8);
    if (lane < S) {
        int s = lane;
        long long e0 = ((long long)(s * B + 0) * N + n) * D;
        long long eb = ((long long)(s * B + b) * N + n) * D;
        #pragma unroll
        for (int d = 0; d < D; d++) {
            sv |= mask_nz(bev_mask, e0 + d, st);
            hv |= mask_nz(bev_mask, eb + d, st);
        }
    }
    unsigned selbits = __ballot_sync(FULL, (lane < S) && sv);
    unsigned hitbits = __ballot_sync(FULL, (lane < S) && hv);
    float inv_cnt = 1.0f / fmaxf((float)__popc(hitbits), 1.0f);

    // note +1.5 = +2 (pad shift) - 0.5 (align_corners=False)
    sm_ox[warp][lane] = oxy.x + 1.5f;
    sm_oy[warp][lane] = oxy.y + 1.5f;
    sm_wp[warp][lane] = aw * inv_cnt;
    __syncwarp();

    const float* oxp = &sm_ox[warp][head << 3];
    const float* oyp = &sm_oy[warp][head << 3];
    const float* wpp = &sm_wp[warp][head << 3];

    float4 acc = make_float4(0.f, 0.f, 0.f, 0.f);
    #pragma unroll
    for (int s = 0; s < S; s++) {
        if (!((selbits >> s) & 1u)) continue;  // warp-uniform
        const __half* vb = g_vproj + (size_t)((s * B + b) * MP) * C + head * 32 + sub * 4;
        const float4* rp4 = (const float4*)(refpts + (((size_t)(s * B + b) * N + n) * D) * 2);
        float4 r0 = __ldg(rp4), r1 = __ldg(rp4 + 1);
        float xb[D] = {r0.x * Wf, r0.z * Wf, r1.x * Wf, r1.z * Wf};
        float yb[D] = {r0.y * Hf, r0.w * Hf, r1.y * Hf, r1.w * Hf};

        #pragma unroll
        for (int p = 0; p < NP; p++) {
            int dz = p & 3;
            float x = xb[dz] + oxp[p];      // padded coords: x = real_x + 2
            float y = yb[dz] + oyp[p];
            float xf = floorf(x), yf = floorf(y);
            float wx1 = x - xf, wy1 = y - yf;
            int px = min(max((int)xf, 0), WP - 2);   // 0..90
            int py = min(max((int)yf, 0), HP - 2);   // 0..34

            const uint2* base = (const uint2*)(vb + (py * WP + px) * C);
            uint2 u00 = __ldg(base);
            uint2 u01 = __ldg(base + (C / 4));
            uint2 u10 = __ldg(base + (WP * C / 4));
            uint2 u11 = __ldg(base + ((WP + 1) * C / 4));

            float wx0 = 1.0f - wx1, wy0 = 1.0f - wy1;
            __half2 hw00 = __float2half2_rn(wy0 * wx0);
            __half2 hw01 = __float2half2_rn(wy0 * wx1);
            __half2 hw10 = __float2half2_rn(wy1 * wx0);
            __half2 hw11 = __float2half2_rn(wy1 * wx1);

            __half2 sa = __hmul2(*(__half2*)&u00.x, hw00);
            sa = __hfma2(*(__half2*)&u01.x, hw01, sa);
            sa = __hfma2(*(__half2*)&u10.x, hw10, sa);
            sa = __hfma2(*(__half2*)&u11.x, hw11, sa);
            __half2 sb = __hmul2(*(__half2*)&u00.y, hw00);
            sb = __hfma2(*(__half2*)&u01.y, hw01, sb);
            sb = __hfma2(*(__half2*)&u10.y, hw10, sb);
            sb = __hfma2(*(__half2*)&u11.y, hw11, sb);

            float wgt = wpp[p];
            float2 fa = __half22float2(sa);
            float2 fb = __half22float2(sb);
            acc.x = fmaf(wgt, fa.x, acc.x);
            acc.y = fmaf(wgt, fa.y, acc.y);
            acc.z = fmaf(wgt, fb.x, acc.z);
            acc.w = fmaf(wgt, fb.y, acc.w);
        }
    }
    *(float4*)(g_slots + (size_t)row * C + lane * 4) = acc;
}

// ---------------------------------------------------------------------------
// Kernel 4: out = slots @ W_out + b_out + query. 64-row tiles, rows guarded.
// ---------------------------------------------------------------------------
__global__ void __launch_bounds__(256) k_out(
    const float* __restrict__ query,  // (B,N,C)
    const float* __restrict__ Wo,     // (C,C)
    const float* __restrict__ bo,     // (C,)
    float* __restrict__ out)          // (B,N,C)
{
    __shared__ float svp[32][64][2];
    const int t   = threadIdx.x;
    const int ro0 = blockIdx.x * 64;
    const int tc  = t & 31;
    const int tm  = t >> 5;

    float2 acc[4][4];
    {
        float4 b4 = __ldg((const float4*)(bo + tc * 4));
        #pragma unroll
        for (int i = 0; i < 4; i++) {
            acc[i][0] = make_float2(b4.x, b4.x);
            acc[i][1] = make_float2(b4.y, b4.y);
            acc[i][2] = make_float2(b4.z, b4.z);
            acc[i][3] = make_float2(b4.w, b4.w);
        }
    }

    for (int kt = 0; kt < 2; kt++) {
        if (kt) __syncthreads();
        for (int idx = t; idx < 64 * 16; idx += 256) {
            int r  = idx >> 4;
            int k4 = (idx & 15) * 4;
            int ro = min(ro0 + r, NROWS - 1);
            float4 v4 = *(const float4*)(g_slots + (size_t)ro * C + kt * 64 + k4);
            svp[r >> 1][k4 + 0][r & 1] = v4.x;
            svp[r >> 1][k4 + 1][r & 1] = v4.y;
            svp[r >> 1][k4 + 2][r & 1] = v4.z;
            svp[r >> 1][k4 + 3][r & 1] = v4.w;
        }
        __syncthreads();

        const float* Wk = Wo + (size_t)(kt * 64) * C + tc * 4;
        #pragma unroll 2
        for (int k = 0; k < 64; k += 2) {
            float4 wa = __ldg((const float4*)(Wk + (size_t)k * C));
            float4 wb = __ldg((const float4*)(Wk + (size_t)(k + 1) * C));
            float2 wpa0 = make_float2(wa.x, wa.x), wpa1 = make_float2(wa.y, wa.y);
            float2 wpa2 = make_float2(wa.z, wa.z), wpa3 = make_float2(wa.w, wa.w);
            float2 wpb0 = make_float2(wb.x, wb.x), wpb1 = make_float2(wb.y, wb.y);
            float2 wpb2 = make_float2(wb.z, wb.z), wpb3 = make_float2(wb.w, wb.w);
            #pragma unroll
            for (int i = 0; i < 4; i++) {
                float4 a4 = *(const float4*)&svp[tm * 4 + i][k][0];
                float2 ak0 = make_float2(a4.x, a4.y);
                float2 ak1 = make_float2(a4.z, a4.w);
                ffma2(acc[i][0], ak0, wpa0); ffma2(acc[i][0], ak1, wpb0);
                ffma2(acc[i][1], ak0, wpa1); ffma2(acc[i][1], ak1, wpb1);
                ffma2(acc[i][2], ak0, wpa2); ffma2(acc[i][2], ak1, wpb2);
                ffma2(acc[i][3], ak0, wpa3); ffma2(acc[i][3], ak1, wpb3);
            }
        }
    }

    #pragma unroll
    for (int i = 0; i < 4; i++) {
        int r0 = ro0 + (tm * 4 + i) * 2;
        #pragma unroll
        for (int par = 0; par < 2; par++) {
            int row = r0 + par;
            if (row >= NROWS) continue;
            size_t off = (size_t)row * C + tc * 4;
            float4 q4 = *(const float4*)(query + off);
            float4 v;
            if (par == 0) v = make_float4(acc[i][0].x + q4.x, acc[i][1].x + q4.y,
                                          acc[i][2].x + q4.z, acc[i][3].x + q4.w);
            else          v = make_float4(acc[i][0].y + q4.x, acc[i][1].y + q4.y,
                                          acc[i][2].y + q4.z, acc[i][3].y + q4.w);
            *(float4*)(out + off) = v;
        }
    }
}

// ---------------------------------------------------------------------------
// Launch. Input order: query, key, value, query_pos, reference_points_cam,
// bev_mask, spatial_shapes, W_value, b_value, W_offsets, b_offsets,
// W_attn, b_attn, W_out, b_out.
// ---------------------------------------------------------------------------
extern "C" void kernel_launch(void* const* d_in, const int* in_sizes, int n_in,
                              void* d_out, int out_size)
{
    const float* query = (const float*)d_in[0];
    // d_in[1] = key: unused by the reference math
    const float* value = (const float*)d_in[2];
    const float* qpos  = (const float*)d_in[3];
    const float* refp  = (const float*)d_in[4];
    const unsigned char* mask = (const unsigned char*)d_in[5];
    // d_in[6] = spatial_shapes (static, hardcoded H=32, W=88)
    const float* Wv   = (const float*)d_in[7];
    const float* bv   = (const float*)d_in[8];
    const float* Woff = (const float*)d_in[9];
    const float* boff = (const float*)d_in[10];
    const float* Wa   = (const float*)d_in[11];
    const float* ba   = (const float*)d_in[12];
    const float* Wo   = (const float*)d_in[13];
    const float* bo   = (const float*)d_in[14];
    float* out = (float*)d_out;

    k_detect  <<<64, 256>>>((const uint4*)mask);
    k_zerofill<<<64, 256>>>();
    k_vproj   <<<(S * B * M) / 64, 256>>>(value, Wv, bv);
    k_qproj   <<<(NROWS + 63) / 64, 256>>>(query, qpos, Woff, boff, Wa, ba);
    k_sample  <<<NROWS / 4, 128>>>(refp, mask);
    k_out     <<<(NROWS + 63) / 64, 256>>>(query, Wo, bo, out);
}

// round 12
// speedup vs baseline: 2.9535x; 1.0839x over previous
#include <cuda_runtime.h>
#include <cuda_fp16.h>

// Problem constants (static per reference)
constexpr int B  = 2;
constexpr int S  = 6;
constexpr int N  = 10000;
constexpr int C  = 128;
constexpr int D  = 4;
constexpr int NH = 4;     // heads
constexpr int NP = 8;     // points
constexpr int Hf = 32;
constexpr int Wf = 88;
constexpr int M  = Hf * Wf;        // 2816
constexpr int WP = Wf + 4;         // 92  (2-px pad each side)
constexpr int HP = Hf + 4;         // 36
constexpr int MP = HP * WP;        // 3312 padded pixels
constexpr int RING = MP - M;       // 496 pad cells per (s,b)
constexpr int MASK_ELEMS = S * B * N * D;  // 480000
constexpr int NROWS = B * N;               // 20000
constexpr int VBLOCKS = (S * B * M) / 64;  // 528 vproj tiles
constexpr int QBLOCKS = (NROWS + 63) / 64; // 313 qproj tiles

// Scratch (device globals; no allocation allowed)
__device__ __half   g_vproj [S * B * MP * C];       // padded (s,b,py,px,c) fp16
__device__ float    g_off   [B * N * NH * NP * 2];  // offsets (pixel units)
__device__ float    g_logits[B * N * NH * NP];      // attn logits
__device__ float    g_slots [B * N * C];            // masked-mean slots
__device__ unsigned g_mask_occ;                     // byte-position occupancy

// packed fp32x2 FMA (Blackwell): d = a*b + d elementwise
__device__ __forceinline__ void ffma2(float2& d, float2 a, float2 b) {
    asm("fma.rn.f32x2 %0, %1, %2, %0;"
        : "+l"(reinterpret_cast<unsigned long long&>(d))
        : "l"(reinterpret_cast<unsigned long long&>(a)),
          "l"(reinterpret_cast<unsigned long long&>(b)));
}

// ---------------------------------------------------------------------------
// Kernel 0: fused mask-dtype probe + pad-ring zerofill (independent work).
// ---------------------------------------------------------------------------
__global__ void k_prep(const uint4* __restrict__ mask16)
{
    const int gtid = blockIdx.x * blockDim.x + threadIdx.x;
    const int gstride = gridDim.x * blockDim.x;

    // --- zero the pad ring of g_vproj ---
    const int total = S * B * RING * 16;   // 95232 uint4 stores
    for (int idx = gtid; idx < total; idx += gstride) {
        int chunk = idx & 15;
        int cellI = idx >> 4;
        int sb = cellI / RING;
        int c  = cellI % RING;
        int py, px;
        if (c < 4 * WP) {                   // rows 0,1,34,35 (full width)
            int rr = c / WP;
            py = (rr < 2) ? rr : rr + 32;
            px = c % WP;
        } else {
            int c2 = c - 4 * WP;
            py = 2 + (c2 >> 2);
            int e = c2 & 3;
            px = (e < 2) ? e : e + 88;
        }
        size_t base = ((size_t)sb * MP + py * WP + px) * C + chunk * 8;
        *(uint4*)&g_vproj[base] = make_uint4(0u, 0u, 0u, 0u);
    }

    // --- mask dtype probe (byte-position occupancy mod 8; OR idempotent) ---
    unsigned occ = 0u;
    const int nvec = MASK_ELEMS / 16;
    for (int i = gtid; i < nvec; i += gstride) {
        uint4 v = __ldg(mask16 + i);
        unsigned w[4] = {v.x, v.y, v.z, v.w};
        #pragma unroll
        for (int wi = 0; wi < 4; wi++) {
            int base = (wi * 4) & 7;
            #pragma unroll
            for (int k = 0; k < 4; k++)
                if ((w[wi] >> (k * 8)) & 0xFFu) occ |= 1u << ((base + k) & 7);
        }
    }
    #pragma unroll
    for (int o = 16; o > 0; o >>= 1) occ |= __shfl_xor_sync(0xffffffffu, occ, o);
    if ((threadIdx.x & 31) == 0 && occ) atomicOr(&g_mask_occ, occ);
}

__device__ __forceinline__ int mask_nz(const unsigned char* __restrict__ mask,
                                       long long elem, int st)
{
    const unsigned char* p = mask + elem * st;
    int v = 0;
    for (int j = 0; j < st; j++) v |= p[j];
    return v != 0;
}

// ---------------------------------------------------------------------------
// vproj tile body: 64 rows, writes fp16 into the PADDED canvas.
// ---------------------------------------------------------------------------
__device__ __forceinline__ void vproj_tile(
    int bid,
    const float* __restrict__ value, const float* __restrict__ Wv,
    const float* __restrict__ bv, float (*svp)[64][2])
{
    const int t   = threadIdx.x;
    const int ro0 = bid * 64;
    const int tc  = t & 31;
    const int tm  = t >> 5;

    float2 acc[4][4];
    {
        float4 b4 = __ldg((const float4*)(bv + tc * 4));
        #pragma unroll
        for (int i = 0; i < 4; i++) {
            acc[i][0] = make_float2(b4.x, b4.x);
            acc[i][1] = make_float2(b4.y, b4.y);
            acc[i][2] = make_float2(b4.z, b4.z);
            acc[i][3] = make_float2(b4.w, b4.w);
        }
    }

    for (int kt = 0; kt < 2; kt++) {
        if (kt) __syncthreads();
        for (int idx = t; idx < 64 * 16; idx += 256) {
            int r  = idx >> 4;
            int k4 = (idx & 15) * 4;
            int ro = ro0 + r;
            int sb = ro / M, m = ro % M;
            int s  = sb / B, bb = sb % B;
            float4 v4 = *(const float4*)(value + ((size_t)((s * M + m) * B + bb) * C + kt * 64 + k4));
            svp[r >> 1][k4 + 0][r & 1] = v4.x;
            svp[r >> 1][k4 + 1][r & 1] = v4.y;
            svp[r >> 1][k4 + 2][r & 1] = v4.z;
            svp[r >> 1][k4 + 3][r & 1] = v4.w;
        }
        __syncthreads();

        const float* Wk = Wv + (size_t)(kt * 64) * C + tc * 4;
        #pragma unroll 2
        for (int k = 0; k < 64; k += 2) {
            float4 wa = __ldg((const float4*)(Wk + (size_t)k * C));
            float4 wb = __ldg((const float4*)(Wk + (size_t)(k + 1) * C));
            float2 wpa0 = make_float2(wa.x, wa.x), wpa1 = make_float2(wa.y, wa.y);
            float2 wpa2 = make_float2(wa.z, wa.z), wpa3 = make_float2(wa.w, wa.w);
            float2 wpb0 = make_float2(wb.x, wb.x), wpb1 = make_float2(wb.y, wb.y);
            float2 wpb2 = make_float2(wb.z, wb.z), wpb3 = make_float2(wb.w, wb.w);
            #pragma unroll
            for (int i = 0; i < 4; i++) {
                float4 a4 = *(const float4*)&svp[tm * 4 + i][k][0];
                float2 ak0 = make_float2(a4.x, a4.y);
                float2 ak1 = make_float2(a4.z, a4.w);
                ffma2(acc[i][0], ak0, wpa0); ffma2(acc[i][0], ak1, wpb0);
                ffma2(acc[i][1], ak0, wpa1); ffma2(acc[i][1], ak1, wpb1);
                ffma2(acc[i][2], ak0, wpa2); ffma2(acc[i][2], ak1, wpb2);
                ffma2(acc[i][3], ak0, wpa3); ffma2(acc[i][3], ak1, wpb3);
            }
        }
    }

    #pragma unroll
    for (int i = 0; i < 4; i++) {
        int r0 = ro0 + (tm * 4 + i) * 2;
        #pragma unroll
        for (int par = 0; par < 2; par++) {
            int ro = r0 + par;
            int sb = ro / M, m = ro % M;
            int y = m / Wf, x = m % Wf;
            size_t pm = (size_t)sb * MP + (y + 2) * WP + (x + 2);
            __half2 h01, h23;
            if (par == 0) {
                h01 = __floats2half2_rn(acc[i][0].x, acc[i][1].x);
                h23 = __floats2half2_rn(acc[i][2].x, acc[i][3].x);
            } else {
                h01 = __floats2half2_rn(acc[i][0].y, acc[i][1].y);
                h23 = __floats2half2_rn(acc[i][2].y, acc[i][3].y);
            }
            uint2 u; u.x = *(unsigned*)&h01; u.y = *(unsigned*)&h23;
            *(uint2*)&g_vproj[pm * C + tc * 4] = u;
        }
    }
}

// ---------------------------------------------------------------------------
// qproj tile body: 64 rows; offsets (64 cols) + logits (32 cols).
// ---------------------------------------------------------------------------
__device__ __forceinline__ void qproj_tile(
    int bid,
    const float* __restrict__ query, const float* __restrict__ qpos,
    const float* __restrict__ Woff, const float* __restrict__ boff,
    const float* __restrict__ Wa,   const float* __restrict__ ba,
    float (*svp)[64][2])
{
    const int t   = threadIdx.x;
    const int ro0 = bid * 64;
    const int tc  = t & 31;
    const int tm  = t >> 5;
    const int c   = tc * 4;
    const bool act = (tc < 24);

    float2 acc[4][4];
    if (act) {
        float4 b4;
        if (c < 64) b4 = *(const float4*)(boff + c);
        else        b4 = *(const float4*)(ba + (c - 64));
        #pragma unroll
        for (int i = 0; i < 4; i++) {
            acc[i][0] = make_float2(b4.x, b4.x);
            acc[i][1] = make_float2(b4.y, b4.y);
            acc[i][2] = make_float2(b4.z, b4.z);
            acc[i][3] = make_float2(b4.w, b4.w);
        }
    }

    for (int kt = 0; kt < 2; kt++) {
        if (kt) __syncthreads();
        for (int idx = t; idx < 64 * 16; idx += 256) {
            int r  = idx >> 4;
            int k4 = (idx & 15) * 4;
            int ro = min(ro0 + r, NROWS - 1);
            size_t off = (size_t)ro * C + kt * 64 + k4;
            float4 a = *(const float4*)(query + off);
            float4 p = *(const float4*)(qpos + off);
            svp[r >> 1][k4 + 0][r & 1] = a.x + p.x;
            svp[r >> 1][k4 + 1][r & 1] = a.y + p.y;
            svp[r >> 1][k4 + 2][r & 1] = a.z + p.z;
            svp[r >> 1][k4 + 3][r & 1] = a.w + p.w;
        }
        __syncthreads();

        if (act) {
            const float* Wk;
            int wstride;
            if (c < 64) { Wk = Woff + (size_t)(kt * 64) * 64 + c;        wstride = 64; }
            else        { Wk = Wa  + (size_t)(kt * 64) * 32 + (c - 64);  wstride = 32; }
            #pragma unroll 2
            for (int k = 0; k < 64; k += 2) {
                float4 wa4 = *(const float4*)(Wk + (size_t)k * wstride);
                float4 wb4 = *(const float4*)(Wk + (size_t)(k + 1) * wstride);
                float2 wpa0 = make_float2(wa4.x, wa4.x), wpa1 = make_float2(wa4.y, wa4.y);
                float2 wpa2 = make_float2(wa4.z, wa4.z), wpa3 = make_float2(wa4.w, wa4.w);
                float2 wpb0 = make_float2(wb4.x, wb4.x), wpb1 = make_float2(wb4.y, wb4.y);
                float2 wpb2 = make_float2(wb4.z, wb4.z), wpb3 = make_float2(wb4.w, wb4.w);
                #pragma unroll
                for (int i = 0; i < 4; i++) {
                    float4 a4 = *(const float4*)&svp[tm * 4 + i][k][0];
                    float2 ak0 = make_float2(a4.x, a4.y);
                    float2 ak1 = make_float2(a4.z, a4.w);
                    ffma2(acc[i][0], ak0, wpa0); ffma2(acc[i][0], ak1, wpb0);
                    ffma2(acc[i][1], ak0, wpa1); ffma2(acc[i][1], ak1, wpb1);
                    ffma2(acc[i][2], ak0, wpa2); ffma2(acc[i][2], ak1, wpb2);
                    ffma2(acc[i][3], ak0, wpa3); ffma2(acc[i][3], ak1, wpb3);
                }
            }
        }
    }

    if (act) {
        #pragma unroll
        for (int i = 0; i < 4; i++) {
            int r0 = ro0 + (tm * 4 + i) * 2;
            #pragma unroll
            for (int par = 0; par < 2; par++) {
                int row = r0 + par;
                if (row >= NROWS) continue;
                float4 v;
                if (par == 0) v = make_float4(acc[i][0].x, acc[i][1].x, acc[i][2].x, acc[i][3].x);
                else          v = make_float4(acc[i][0].y, acc[i][1].y, acc[i][2].y, acc[i][3].y);
                if (c < 64) *(float4*)(g_off    + (size_t)row * 64 + c)        = v;
                else        *(float4*)(g_logits + (size_t)row * 32 + (c - 64)) = v;
            }
        }
    }
}

// ---------------------------------------------------------------------------
// Kernel 1: FUSED vproj + qproj (independent GEMMs share one launch so their
// waves interleave across SMs -> qproj hides in vproj's occupancy holes).
// ---------------------------------------------------------------------------
__global__ void __launch_bounds__(256) k_proj(
    const float* __restrict__ value, const float* __restrict__ Wv,
    const float* __restrict__ bv,
    const float* __restrict__ query, const float* __restrict__ qpos,
    const float* __restrict__ Woff,  const float* __restrict__ boff,
    const float* __restrict__ Wa,    const float* __restrict__ ba)
{
    __shared__ float svp[32][64][2];  // 16KB, shared by both paths
    if (blockIdx.x < VBLOCKS)
        vproj_tile(blockIdx.x, value, Wv, bv, svp);
    else
        qproj_tile(blockIdx.x - VBLOCKS, query, qpos, Woff, boff, Wa, ba, svp);
}

// ---------------------------------------------------------------------------
// Kernel 2: bilinear deformable sampling, ONE WARP PER QUERY, fp16 padded
// canvas, branchless clamp into zero ring. (unchanged from R11)
// ---------------------------------------------------------------------------
__global__ void __launch_bounds__(128, 10) k_sample(
    const float* __restrict__ refpts,           // (S,B,N,D,2)
    const unsigned char* __restrict__ bev_mask) // (S,B,N,D), stride detected
{
    const unsigned FULL = 0xffffffffu;
    const int warp = threadIdx.x >> 5;
    const int lane = threadIdx.x & 31;
    const int row  = blockIdx.x * 4 + warp;  // b*N + n
    const int b    = row / N;
    const int n    = row % N;
    const int head = lane >> 3;
    const int sub  = lane & 7;

    __shared__ float sm_ox[4][32];
    __shared__ float sm_oy[4][32];
    __shared__ float sm_wp[4][32];

    float l = __ldg(g_logits + row * 32 + lane);   // lane = head*8 + p
    float mx = l;
    #pragma unroll
    for (int o = 4; o > 0; o >>= 1) mx = fmaxf(mx, __shfl_xor_sync(FULL, mx, o, 8));
    float e = expf(l - mx);
    float ssum = e;
    #pragma unroll
    for (int o = 4; o > 0; o >>= 1) ssum += __shfl_xor_sync(FULL, ssum, o, 8);
    float aw = e / ssum;

    float2 oxy = __ldg((const float2*)(g_off + row * 64) + lane);

    int sv = 0, hv = 0;
    unsigned occ = g_mask_occ;
    int st = (occ & 0x22u) ? 1 : ((occ & 0x1Cu) ? 4 : 8);
    if (lane < S) {
        int s = lane;
        long long e0 = ((long long)(s * B + 0) * N + n) * D;
        long long eb = ((long long)(s * B + b) * N + n) * D;
        #pragma unroll
        for (int d = 0; d < D; d++) {
            sv |= mask_nz(bev_mask, e0 + d, st);
            hv |= mask_nz(bev_mask, eb + d, st);
        }
    }
    unsigned selbits = __ballot_sync(FULL, (lane < S) && sv);
    unsigned hitbits = __ballot_sync(FULL, (lane < S) && hv);
    float inv_cnt = 1.0f / fmaxf((float)__popc(hitbits), 1.0f);

    // +1.5 = +2 (pad shift) - 0.5 (align_corners=False)
    sm_ox[warp][lane] = oxy.x + 1.5f;
    sm_oy[warp][lane] = oxy.y + 1.5f;
    sm_wp[warp][lane] = aw * inv_cnt;
    __syncwarp();

    const float* oxp = &sm_ox[warp][head << 3];
    const float* oyp = &sm_oy[warp][head << 3];
    const float* wpp = &sm_wp[warp][head << 3];

    float4 acc = make_float4(0.f, 0.f, 0.f, 0.f);
    #pragma unroll
    for (int s = 0; s < S; s++) {
        if (!((selbits >> s) & 1u)) continue;  // warp-uniform
        const __half* vb = g_vproj + (size_t)((s * B + b) * MP) * C + head * 32 + sub * 4;
        const float4* rp4 = (const float4*)(refpts + (((size_t)(s * B + b) * N + n) * D) * 2);
        float4 r0 = __ldg(rp4), r1 = __ldg(rp4 + 1);
        float xb[D] = {r0.x * Wf, r0.z * Wf, r1.x * Wf, r1.z * Wf};
        float yb[D] = {r0.y * Hf, r0.w * Hf, r1.y * Hf, r1.w * Hf};

        #pragma unroll
        for (int p = 0; p < NP; p++) {
            int dz = p & 3;
            float x = xb[dz] + oxp[p];      // padded coords
            float y = yb[dz] + oyp[p];
            float xf = floorf(x), yf = floorf(y);
            float wx1 = x - xf, wy1 = y - yf;
            int px = min(max((int)xf, 0), WP - 2);
            int py = min(max((int)yf, 0), HP - 2);

            const uint2* base = (const uint2*)(vb + (py * WP + px) * C);
            uint2 u00 = __ldg(base);
            uint2 u01 = __ldg(base + (C / 4));
            uint2 u10 = __ldg(base + (WP * C / 4));
            uint2 u11 = __ldg(base + ((WP + 1) * C / 4));

            float wx0 = 1.0f - wx1, wy0 = 1.0f - wy1;
            __half2 hw00 = __float2half2_rn(wy0 * wx0);
            __half2 hw01 = __float2half2_rn(wy0 * wx1);
            __half2 hw10 = __float2half2_rn(wy1 * wx0);
            __half2 hw11 = __float2half2_rn(wy1 * wx1);

            __half2 sa = __hmul2(*(__half2*)&u00.x, hw00);
            sa = __hfma2(*(__half2*)&u01.x, hw01, sa);
            sa = __hfma2(*(__half2*)&u10.x, hw10, sa);
            sa = __hfma2(*(__half2*)&u11.x, hw11, sa);
            __half2 sb = __hmul2(*(__half2*)&u00.y, hw00);
            sb = __hfma2(*(__half2*)&u01.y, hw01, sb);
            sb = __hfma2(*(__half2*)&u10.y, hw10, sb);
            sb = __hfma2(*(__half2*)&u11.y, hw11, sb);

            float wgt = wpp[p];
            float2 fa = __half22float2(sa);
            float2 fb = __half22float2(sb);
            acc.x = fmaf(wgt, fa.x, acc.x);
            acc.y = fmaf(wgt, fa.y, acc.y);
            acc.z = fmaf(wgt, fb.x, acc.z);
            acc.w = fmaf(wgt, fb.y, acc.w);
        }
    }
    *(float4*)(g_slots + (size_t)row * C + lane * 4) = acc;
}

// ---------------------------------------------------------------------------
// Kernel 3: out = slots @ W_out + b_out + query. 64-row tiles, rows guarded.
// ---------------------------------------------------------------------------
__global__ void __launch_bounds__(256) k_out(
    const float* __restrict__ query,  // (B,N,C)
    const float* __restrict__ Wo,     // (C,C)
    const float* __restrict__ bo,     // (C,)
    float* __restrict__ out)          // (B,N,C)
{
    __shared__ float svp[32][64][2];
    const int t   = threadIdx.x;
    const int ro0 = blockIdx.x * 64;
    const int tc  = t & 31;
    const int tm  = t >> 5;

    float2 acc[4][4];
    {
        float4 b4 = __ldg((const float4*)(bo + tc * 4));
        #pragma unroll
        for (int i = 0; i < 4; i++) {
            acc[i][0] = make_float2(b4.x, b4.x);
            acc[i][1] = make_float2(b4.y, b4.y);
            acc[i][2] = make_float2(b4.z, b4.z);
            acc[i][3] = make_float2(b4.w, b4.w);
        }
    }

    for (int kt = 0; kt < 2; kt++) {
        if (kt) __syncthreads();
        for (int idx = t; idx < 64 * 16; idx += 256) {
            int r  = idx >> 4;
            int k4 = (idx & 15) * 4;
            int ro = min(ro0 + r, NROWS - 1);
            float4 v4 = *(const float4*)(g_slots + (size_t)ro * C + kt * 64 + k4);
            svp[r >> 1][k4 + 0][r & 1] = v4.x;
            svp[r >> 1][k4 + 1][r & 1] = v4.y;
            svp[r >> 1][k4 + 2][r & 1] = v4.z;
            svp[r >> 1][k4 + 3][r & 1] = v4.w;
        }
        __syncthreads();

        const float* Wk = Wo + (size_t)(kt * 64) * C + tc * 4;
        #pragma unroll 2
        for (int k = 0; k < 64; k += 2) {
            float4 wa = __ldg((const float4*)(Wk + (size_t)k * C));
            float4 wb = __ldg((const float4*)(Wk + (size_t)(k + 1) * C));
            float2 wpa0 = make_float2(wa.x, wa.x), wpa1 = make_float2(wa.y, wa.y);
            float2 wpa2 = make_float2(wa.z, wa.z), wpa3 = make_float2(wa.w, wa.w);
            float2 wpb0 = make_float2(wb.x, wb.x), wpb1 = make_float2(wb.y, wb.y);
            float2 wpb2 = make_float2(wb.z, wb.z), wpb3 = make_float2(wb.w, wb.w);
            #pragma unroll
            for (int i = 0; i < 4; i++) {
                float4 a4 = *(const float4*)&svp[tm * 4 + i][k][0];
                float2 ak0 = make_float2(a4.x, a4.y);
                float2 ak1 = make_float2(a4.z, a4.w);
                ffma2(acc[i][0], ak0, wpa0); ffma2(acc[i][0], ak1, wpb0);
                ffma2(acc[i][1], ak0, wpa1); ffma2(acc[i][1], ak1, wpb1);
                ffma2(acc[i][2], ak0, wpa2); ffma2(acc[i][2], ak1, wpb2);
                ffma2(acc[i][3], ak0, wpa3); ffma2(acc[i][3], ak1, wpb3);
            }
        }
    }

    #pragma unroll
    for (int i = 0; i < 4; i++) {
        int r0 = ro0 + (tm * 4 + i) * 2;
        #pragma unroll
        for (int par = 0; par < 2; par++) {
            int row = r0 + par;
            if (row >= NROWS) continue;
            size_t off = (size_t)row * C + tc * 4;
            float4 q4 = *(const float4*)(query + off);
            float4 v;
            if (par == 0) v = make_float4(acc[i][0].x + q4.x, acc[i][1].x + q4.y,
                                          acc[i][2].x + q4.z, acc[i][3].x + q4.w);
            else          v = make_float4(acc[i][0].y + q4.x, acc[i][1].y + q4.y,
                                          acc[i][2].y + q4.z, acc[i][3].y + q4.w);
            *(float4*)(out + off) = v;
        }
    }
}

// ---------------------------------------------------------------------------
// Launch. Input order: query, key, value, query_pos, reference_points_cam,
// bev_mask, spatial_shapes, W_value, b_value, W_offsets, b_offsets,
// W_attn, b_attn, W_out, b_out.
// ---------------------------------------------------------------------------
extern "C" void kernel_launch(void* const* d_in, const int* in_sizes, int n_in,
                              void* d_out, int out_size)
{
    const float* query = (const float*)d_in[0];
    // d_in[1] = key: unused by the reference math
    const float* value = (const float*)d_in[2];
    const float* qpos  = (const float*)d_in[3];
    const float* refp  = (const float*)d_in[4];
    const unsigned char* mask = (const unsigned char*)d_in[5];
    // d_in[6] = spatial_shapes (static, hardcoded H=32, W=88)
    const float* Wv   = (const float*)d_in[7];
    const float* bv   = (const float*)d_in[8];
    const float* Woff = (const float*)d_in[9];
    const float* boff = (const float*)d_in[10];
    const float* Wa   = (const float*)d_in[11];
    const float* ba   = (const float*)d_in[12];
    const float* Wo   = (const float*)d_in[13];
    const float* bo   = (const float*)d_in[14];
    float* out = (float*)d_out;

    k_prep  <<<148, 256>>>((const uint4*)mask);
    k_proj  <<<VBLOCKS + QBLOCKS, 256>>>(value, Wv, bv, query, qpos, Woff, boff, Wa, ba);
    k_sample<<<NROWS / 4, 128>>>(refp, mask);
    k_out   <<<QBLOCKS, 256>>>(query, Wo, bo, out);
}

// round 13
// speedup vs baseline: 2.9896x; 1.0122x over previous
#include <cuda_runtime.h>
#include <cuda_fp16.h>

// Problem constants (static per reference)
constexpr int B  = 2;
constexpr int S  = 6;
constexpr int N  = 10000;
constexpr int C  = 128;
constexpr int D  = 4;
constexpr int NH = 4;     // heads
constexpr int NP = 8;     // points
constexpr int Hf = 32;
constexpr int Wf = 88;
constexpr int M  = Hf * Wf;        // 2816
constexpr int WP = Wf + 4;         // 92  (2-px pad each side)
constexpr int HP = Hf + 4;         // 36
constexpr int MP = HP * WP;        // 3312 padded pixels
constexpr int RING = MP - M;       // 496 pad cells per (s,b)
constexpr int MASK_ELEMS = S * B * N * D;  // 480000
constexpr int NROWS = B * N;               // 20000
constexpr int VBLOCKS = (S * B * M) / 64;  // 528 vproj tiles
constexpr int QBLOCKS = (NROWS + 63) / 64; // 313 qproj tiles
constexpr int OBLOCKS = (NROWS + 31) / 32; // 625 out tiles

// Scratch (device globals; no allocation allowed)
__device__ __half   g_vproj [S * B * MP * C];       // padded (s,b,py,px,c) fp16
__device__ float    g_off   [B * N * NH * NP * 2];  // offsets (pixel units)
__device__ float    g_logits[B * N * NH * NP];      // attn logits
__device__ float    g_slots [B * N * C];            // masked-mean slots
__device__ unsigned g_mask_occ;                     // byte-position occupancy

// packed fp32x2 FMA (Blackwell): d = a*b + d elementwise
__device__ __forceinline__ void ffma2(float2& d, float2 a, float2 b) {
    asm("fma.rn.f32x2 %0, %1, %2, %0;"
        : "+l"(reinterpret_cast<unsigned long long&>(d))
        : "l"(reinterpret_cast<unsigned long long&>(a)),
          "l"(reinterpret_cast<unsigned long long&>(b)));
}

// ---------------------------------------------------------------------------
// Kernel 0: fused mask-dtype probe + pad-ring zerofill (independent work).
// ---------------------------------------------------------------------------
__global__ void k_prep(const uint4* __restrict__ mask16)
{
    const int gtid = blockIdx.x * blockDim.x + threadIdx.x;
    const int gstride = gridDim.x * blockDim.x;

    // --- zero the pad ring of g_vproj ---
    const int total = S * B * RING * 16;   // 95232 uint4 stores
    for (int idx = gtid; idx < total; idx += gstride) {
        int chunk = idx & 15;
        int cellI = idx >> 4;
        int sb = cellI / RING;
        int c  = cellI % RING;
        int py, px;
        if (c < 4 * WP) {                   // rows 0,1,34,35 (full width)
            int rr = c / WP;
            py = (rr < 2) ? rr : rr + 32;
            px = c % WP;
        } else {
            int c2 = c - 4 * WP;
            py = 2 + (c2 >> 2);
            int e = c2 & 3;
            px = (e < 2) ? e : e + 88;
        }
        size_t base = ((size_t)sb * MP + py * WP + px) * C + chunk * 8;
        *(uint4*)&g_vproj[base] = make_uint4(0u, 0u, 0u, 0u);
    }

    // --- mask dtype probe (byte-position occupancy mod 8; OR idempotent) ---
    unsigned occ = 0u;
    const int nvec = MASK_ELEMS / 16;
    for (int i = gtid; i < nvec; i += gstride) {
        uint4 v = __ldg(mask16 + i);
        unsigned w[4] = {v.x, v.y, v.z, v.w};
        #pragma unroll
        for (int wi = 0; wi < 4; wi++) {
            int base = (wi * 4) & 7;
            #pragma unroll
            for (int k = 0; k < 4; k++)
                if ((w[wi] >> (k * 8)) & 0xFFu) occ |= 1u << ((base + k) & 7);
        }
    }
    #pragma unroll
    for (int o = 16; o > 0; o >>= 1) occ |= __shfl_xor_sync(0xffffffffu, occ, o);
    if ((threadIdx.x & 31) == 0 && occ) atomicOr(&g_mask_occ, occ);
}

__device__ __forceinline__ int mask_nz(const unsigned char* __restrict__ mask,
                                       long long elem, int st)
{
    const unsigned char* p = mask + elem * st;
    int v = 0;
    for (int j = 0; j < st; j++) v |= p[j];
    return v != 0;
}

// ---------------------------------------------------------------------------
// vproj tile body: 64 rows, writes fp16 into the PADDED canvas.
// ---------------------------------------------------------------------------
__device__ __forceinline__ void vproj_tile(
    int bid,
    const float* __restrict__ value, const float* __restrict__ Wv,
    const float* __restrict__ bv, float (*svp)[64][2])
{
    const int t   = threadIdx.x;
    const int ro0 = bid * 64;
    const int tc  = t & 31;
    const int tm  = t >> 5;

    float2 acc[4][4];
    {
        float4 b4 = __ldg((const float4*)(bv + tc * 4));
        #pragma unroll
        for (int i = 0; i < 4; i++) {
            acc[i][0] = make_float2(b4.x, b4.x);
            acc[i][1] = make_float2(b4.y, b4.y);
            acc[i][2] = make_float2(b4.z, b4.z);
            acc[i][3] = make_float2(b4.w, b4.w);
        }
    }

    for (int kt = 0; kt < 2; kt++) {
        if (kt) __syncthreads();
        for (int idx = t; idx < 64 * 16; idx += 256) {
            int r  = idx >> 4;
            int k4 = (idx & 15) * 4;
            int ro = ro0 + r;
            int sb = ro / M, m = ro % M;
            int s  = sb / B, bb = sb % B;
            float4 v4 = *(const float4*)(value + ((size_t)((s * M + m) * B + bb) * C + kt * 64 + k4));
            svp[r >> 1][k4 + 0][r & 1] = v4.x;
            svp[r >> 1][k4 + 1][r & 1] = v4.y;
            svp[r >> 1][k4 + 2][r & 1] = v4.z;
            svp[r >> 1][k4 + 3][r & 1] = v4.w;
        }
        __syncthreads();

        const float* Wk = Wv + (size_t)(kt * 64) * C + tc * 4;
        #pragma unroll 2
        for (int k = 0; k < 64; k += 2) {
            float4 wa = __ldg((const float4*)(Wk + (size_t)k * C));
            float4 wb = __ldg((const float4*)(Wk + (size_t)(k + 1) * C));
            float2 wpa0 = make_float2(wa.x, wa.x), wpa1 = make_float2(wa.y, wa.y);
            float2 wpa2 = make_float2(wa.z, wa.z), wpa3 = make_float2(wa.w, wa.w);
            float2 wpb0 = make_float2(wb.x, wb.x), wpb1 = make_float2(wb.y, wb.y);
            float2 wpb2 = make_float2(wb.z, wb.z), wpb3 = make_float2(wb.w, wb.w);
            #pragma unroll
            for (int i = 0; i < 4; i++) {
                float4 a4 = *(const float4*)&svp[tm * 4 + i][k][0];
                float2 ak0 = make_float2(a4.x, a4.y);
                float2 ak1 = make_float2(a4.z, a4.w);
                ffma2(acc[i][0], ak0, wpa0); ffma2(acc[i][0], ak1, wpb0);
                ffma2(acc[i][1], ak0, wpa1); ffma2(acc[i][1], ak1, wpb1);
                ffma2(acc[i][2], ak0, wpa2); ffma2(acc[i][2], ak1, wpb2);
                ffma2(acc[i][3], ak0, wpa3); ffma2(acc[i][3], ak1, wpb3);
            }
        }
    }

    #pragma unroll
    for (int i = 0; i < 4; i++) {
        int r0 = ro0 + (tm * 4 + i) * 2;
        #pragma unroll
        for (int par = 0; par < 2; par++) {
            int ro = r0 + par;
            int sb = ro / M, m = ro % M;
            int y = m / Wf, x = m % Wf;
            size_t pm = (size_t)sb * MP + (y + 2) * WP + (x + 2);
            __half2 h01, h23;
            if (par == 0) {
                h01 = __floats2half2_rn(acc[i][0].x, acc[i][1].x);
                h23 = __floats2half2_rn(acc[i][2].x, acc[i][3].x);
            } else {
                h01 = __floats2half2_rn(acc[i][0].y, acc[i][1].y);
                h23 = __floats2half2_rn(acc[i][2].y, acc[i][3].y);
            }
            uint2 u; u.x = *(unsigned*)&h01; u.y = *(unsigned*)&h23;
            *(uint2*)&g_vproj[pm * C + tc * 4] = u;
        }
    }
}

// ---------------------------------------------------------------------------
// qproj tile body: 64 rows; offsets (64 cols) + logits (32 cols).
// ---------------------------------------------------------------------------
__device__ __forceinline__ void qproj_tile(
    int bid,
    const float* __restrict__ query, const float* __restrict__ qpos,
    const float* __restrict__ Woff, const float* __restrict__ boff,
    const float* __restrict__ Wa,   const float* __restrict__ ba,
    float (*svp)[64][2])
{
    const int t   = threadIdx.x;
    const int ro0 = bid * 64;
    const int tc  = t & 31;
    const int tm  = t >> 5;
    const int c   = tc * 4;
    const bool act = (tc < 24);

    float2 acc[4][4];
    if (act) {
        float4 b4;
        if (c < 64) b4 = *(const float4*)(boff + c);
        else        b4 = *(const float4*)(ba + (c - 64));
        #pragma unroll
        for (int i = 0; i < 4; i++) {
            acc[i][0] = make_float2(b4.x, b4.x);
            acc[i][1] = make_float2(b4.y, b4.y);
            acc[i][2] = make_float2(b4.z, b4.z);
            acc[i][3] = make_float2(b4.w, b4.w);
        }
    }

    for (int kt = 0; kt < 2; kt++) {
        if (kt) __syncthreads();
        for (int idx = t; idx < 64 * 16; idx += 256) {
            int r  = idx >> 4;
            int k4 = (idx & 15) * 4;
            int ro = min(ro0 + r, NROWS - 1);
            size_t off = (size_t)ro * C + kt * 64 + k4;
            float4 a = *(const float4*)(query + off);
            float4 p = *(const float4*)(qpos + off);
            svp[r >> 1][k4 + 0][r & 1] = a.x + p.x;
            svp[r >> 1][k4 + 1][r & 1] = a.y + p.y;
            svp[r >> 1][k4 + 2][r & 1] = a.z + p.z;
            svp[r >> 1][k4 + 3][r & 1] = a.w + p.w;
        }
        __syncthreads();

        if (act) {
            const float* Wk;
            int wstride;
            if (c < 64) { Wk = Woff + (size_t)(kt * 64) * 64 + c;        wstride = 64; }
            else        { Wk = Wa  + (size_t)(kt * 64) * 32 + (c - 64);  wstride = 32; }
            #pragma unroll 2
            for (int k = 0; k < 64; k += 2) {
                float4 wa4 = *(const float4*)(Wk + (size_t)k * wstride);
                float4 wb4 = *(const float4*)(Wk + (size_t)(k + 1) * wstride);
                float2 wpa0 = make_float2(wa4.x, wa4.x), wpa1 = make_float2(wa4.y, wa4.y);
                float2 wpa2 = make_float2(wa4.z, wa4.z), wpa3 = make_float2(wa4.w, wa4.w);
                float2 wpb0 = make_float2(wb4.x, wb4.x), wpb1 = make_float2(wb4.y, wb4.y);
                float2 wpb2 = make_float2(wb4.z, wb4.z), wpb3 = make_float2(wb4.w, wb4.w);
                #pragma unroll
                for (int i = 0; i < 4; i++) {
                    float4 a4 = *(const float4*)&svp[tm * 4 + i][k][0];
                    float2 ak0 = make_float2(a4.x, a4.y);
                    float2 ak1 = make_float2(a4.z, a4.w);
                    ffma2(acc[i][0], ak0, wpa0); ffma2(acc[i][0], ak1, wpb0);
                    ffma2(acc[i][1], ak0, wpa1); ffma2(acc[i][1], ak1, wpb1);
                    ffma2(acc[i][2], ak0, wpa2); ffma2(acc[i][2], ak1, wpb2);
                    ffma2(acc[i][3], ak0, wpa3); ffma2(acc[i][3], ak1, wpb3);
                }
            }
        }
    }

    if (act) {
        #pragma unroll
        for (int i = 0; i < 4; i++) {
            int r0 = ro0 + (tm * 4 + i) * 2;
            #pragma unroll
            for (int par = 0; par < 2; par++) {
                int row = r0 + par;
                if (row >= NROWS) continue;
                float4 v;
                if (par == 0) v = make_float4(acc[i][0].x, acc[i][1].x, acc[i][2].x, acc[i][3].x);
                else          v = make_float4(acc[i][0].y, acc[i][1].y, acc[i][2].y, acc[i][3].y);
                if (c < 64) *(float4*)(g_off    + (size_t)row * 64 + c)        = v;
                else        *(float4*)(g_logits + (size_t)row * 32 + (c - 64)) = v;
            }
        }
    }
}

// ---------------------------------------------------------------------------
// Kernel 1: FUSED vproj + qproj.
// ---------------------------------------------------------------------------
__global__ void __launch_bounds__(256) k_proj(
    const float* __restrict__ value, const float* __restrict__ Wv,
    const float* __restrict__ bv,
    const float* __restrict__ query, const float* __restrict__ qpos,
    const float* __restrict__ Woff,  const float* __restrict__ boff,
    const float* __restrict__ Wa,    const float* __restrict__ ba)
{
    __shared__ float svp[32][64][2];  // 16KB, shared by both paths
    if (blockIdx.x < VBLOCKS)
        vproj_tile(blockIdx.x, value, Wv, bv, svp);
    else
        qproj_tile(blockIdx.x - VBLOCKS, query, qpos, Woff, boff, Wa, ba, svp);
}

// ---------------------------------------------------------------------------
// Kernel 2: bilinear deformable sampling, ONE WARP PER QUERY, fp16 padded
// canvas, branchless clamp into zero ring. (unchanged)
// ---------------------------------------------------------------------------
__global__ void __launch_bounds__(128, 10) k_sample(
    const float* __restrict__ refpts,           // (S,B,N,D,2)
    const unsigned char* __restrict__ bev_mask) // (S,B,N,D), stride detected
{
    const unsigned FULL = 0xffffffffu;
    const int warp = threadIdx.x >> 5;
    const int lane = threadIdx.x & 31;
    const int row  = blockIdx.x * 4 + warp;  // b*N + n
    const int b    = row / N;
    const int n    = row % N;
    const int head = lane >> 3;
    const int sub  = lane & 7;

    __shared__ float sm_ox[4][32];
    __shared__ float sm_oy[4][32];
    __shared__ float sm_wp[4][32];

    float l = __ldg(g_logits + row * 32 + lane);   // lane = head*8 + p
    float mx = l;
    #pragma unroll
    for (int o = 4; o > 0; o >>= 1) mx = fmaxf(mx, __shfl_xor_sync(FULL, mx, o, 8));
    float e = expf(l - mx);
    float ssum = e;
    #pragma unroll
    for (int o = 4; o > 0; o >>= 1) ssum += __shfl_xor_sync(FULL, ssum, o, 8);
    float aw = e / ssum;

    float2 oxy = __ldg((const float2*)(g_off + row * 64) + lane);

    int sv = 0, hv = 0;
    unsigned occ = g_mask_occ;
    int st = (occ & 0x22u) ? 1 : ((occ & 0x1Cu) ? 4 : 8);
    if (lane < S) {
        int s = lane;
        long long e0 = ((long long)(s * B + 0) * N + n) * D;
        long long eb = ((long long)(s * B + b) * N + n) * D;
        #pragma unroll
        for (int d = 0; d < D; d++) {
            sv |= mask_nz(bev_mask, e0 + d, st);
            hv |= mask_nz(bev_mask, eb + d, st);
        }
    }
    unsigned selbits = __ballot_sync(FULL, (lane < S) && sv);
    unsigned hitbits = __ballot_sync(FULL, (lane < S) && hv);
    float inv_cnt = 1.0f / fmaxf((float)__popc(hitbits), 1.0f);

    // +1.5 = +2 (pad shift) - 0.5 (align_corners=False)
    sm_ox[warp][lane] = oxy.x + 1.5f;
    sm_oy[warp][lane] = oxy.y + 1.5f;
    sm_wp[warp][lane] = aw * inv_cnt;
    __syncwarp();

    const float* oxp = &sm_ox[warp][head << 3];
    const float* oyp = &sm_oy[warp][head << 3];
    const float* wpp = &sm_wp[warp][head << 3];

    float4 acc = make_float4(0.f, 0.f, 0.f, 0.f);
    #pragma unroll
    for (int s = 0; s < S; s++) {
        if (!((selbits >> s) & 1u)) continue;  // warp-uniform
        const __half* vb = g_vproj + (size_t)((s * B + b) * MP) * C + head * 32 + sub * 4;
        const float4* rp4 = (const float4*)(refpts + (((size_t)(s * B + b) * N + n) * D) * 2);
        float4 r0 = __ldg(rp4), r1 = __ldg(rp4 + 1);
        float xb[D] = {r0.x * Wf, r0.z * Wf, r1.x * Wf, r1.z * Wf};
        float yb[D] = {r0.y * Hf, r0.w * Hf, r1.y * Hf, r1.w * Hf};

        #pragma unroll
        for (int p = 0; p < NP; p++) {
            int dz = p & 3;
            float x = xb[dz] + oxp[p];      // padded coords
            float y = yb[dz] + oyp[p];
            float xf = floorf(x), yf = floorf(y);
            float wx1 = x - xf, wy1 = y - yf;
            int px = min(max((int)xf, 0), WP - 2);
            int py = min(max((int)yf, 0), HP - 2);

            const uint2* base = (const uint2*)(vb + (py * WP + px) * C);
            uint2 u00 = __ldg(base);
            uint2 u01 = __ldg(base + (C / 4));
            uint2 u10 = __ldg(base + (WP * C / 4));
            uint2 u11 = __ldg(base + ((WP + 1) * C / 4));

            float wx0 = 1.0f - wx1, wy0 = 1.0f - wy1;
            __half2 hw00 = __float2half2_rn(wy0 * wx0);
            __half2 hw01 = __float2half2_rn(wy0 * wx1);
            __half2 hw10 = __float2half2_rn(wy1 * wx0);
            __half2 hw11 = __float2half2_rn(wy1 * wx1);

            __half2 sa = __hmul2(*(__half2*)&u00.x, hw00);
            sa = __hfma2(*(__half2*)&u01.x, hw01, sa);
            sa = __hfma2(*(__half2*)&u10.x, hw10, sa);
            sa = __hfma2(*(__half2*)&u11.x, hw11, sa);
            __half2 sb = __hmul2(*(__half2*)&u00.y, hw00);
            sb = __hfma2(*(__half2*)&u01.y, hw01, sb);
            sb = __hfma2(*(__half2*)&u10.y, hw10, sb);
            sb = __hfma2(*(__half2*)&u11.y, hw11, sb);

            float wgt = wpp[p];
            float2 fa = __half22float2(sa);
            float2 fb = __half22float2(sb);
            acc.x = fmaf(wgt, fa.x, acc.x);
            acc.y = fmaf(wgt, fa.y, acc.y);
            acc.z = fmaf(wgt, fb.x, acc.z);
            acc.w = fmaf(wgt, fb.y, acc.w);
        }
    }
    *(float4*)(g_slots + (size_t)row * C + lane * 4) = acc;
}

// ---------------------------------------------------------------------------
// Kernel 3: out = slots @ W_out + b_out + query. 32-row tiles (625 blocks)
// for grid parallelism; 8 warps x 2 row-pairs each.
// ---------------------------------------------------------------------------
__global__ void __launch_bounds__(256) k_out(
    const float* __restrict__ query,  // (B,N,C)
    const float* __restrict__ Wo,     // (C,C)
    const float* __restrict__ bo,     // (C,)
    float* __restrict__ out)          // (B,N,C)
{
    __shared__ float svp[16][64][2];  // 8KB: 16 row-pairs x 64 k x 2
    const int t   = threadIdx.x;
    const int ro0 = blockIdx.x * 32;
    const int tc  = t & 31;
    const int tm  = t >> 5;

    float2 acc[2][4];
    {
        float4 b4 = __ldg((const float4*)(bo + tc * 4));
        #pragma unroll
        for (int i = 0; i < 2; i++) {
            acc[i][0] = make_float2(b4.x, b4.x);
            acc[i][1] = make_float2(b4.y, b4.y);
            acc[i][2] = make_float2(b4.z, b4.z);
            acc[i][3] = make_float2(b4.w, b4.w);
        }
    }

    for (int kt = 0; kt < 2; kt++) {
        if (kt) __syncthreads();
        for (int idx = t; idx < 32 * 16; idx += 256) {
            int r  = idx >> 4;
            int k4 = (idx & 15) * 4;
            int ro = min(ro0 + r, NROWS - 1);
            float4 v4 = *(const float4*)(g_slots + (size_t)ro * C + kt * 64 + k4);
            svp[r >> 1][k4 + 0][r & 1] = v4.x;
            svp[r >> 1][k4 + 1][r & 1] = v4.y;
            svp[r >> 1][k4 + 2][r & 1] = v4.z;
            svp[r >> 1][k4 + 3][r & 1] = v4.w;
        }
        __syncthreads();

        const float* Wk = Wo + (size_t)(kt * 64) * C + tc * 4;
        #pragma unroll 2
        for (int k = 0; k < 64; k += 2) {
            float4 wa = __ldg((const float4*)(Wk + (size_t)k * C));
            float4 wb = __ldg((const float4*)(Wk + (size_t)(k + 1) * C));
            float2 wpa0 = make_float2(wa.x, wa.x), wpa1 = make_float2(wa.y, wa.y);
            float2 wpa2 = make_float2(wa.z, wa.z), wpa3 = make_float2(wa.w, wa.w);
            float2 wpb0 = make_float2(wb.x, wb.x), wpb1 = make_float2(wb.y, wb.y);
            float2 wpb2 = make_float2(wb.z, wb.z), wpb3 = make_float2(wb.w, wb.w);
            #pragma unroll
            for (int i = 0; i < 2; i++) {
                float4 a4 = *(const float4*)&svp[tm * 2 + i][k][0];
                float2 ak0 = make_float2(a4.x, a4.y);
                float2 ak1 = make_float2(a4.z, a4.w);
                ffma2(acc[i][0], ak0, wpa0); ffma2(acc[i][0], ak1, wpb0);
                ffma2(acc[i][1], ak0, wpa1); ffma2(acc[i][1], ak1, wpb1);
                ffma2(acc[i][2], ak0, wpa2); ffma2(acc[i][2], ak1, wpb2);
                ffma2(acc[i][3], ak0, wpa3); ffma2(acc[i][3], ak1, wpb3);
            }
        }
    }

    #pragma unroll
    for (int i = 0; i < 2; i++) {
        int r0 = ro0 + (tm * 2 + i) * 2;
        #pragma unroll
        for (int par = 0; par < 2; par++) {
            int row = r0 + par;
            if (row >= NROWS) continue;
            size_t off = (size_t)row * C + tc * 4;
            float4 q4 = *(const float4*)(query + off);
            float4 v;
            if (par == 0) v = make_float4(acc[i][0].x + q4.x, acc[i][1].x + q4.y,
                                          acc[i][2].x + q4.z, acc[i][3].x + q4.w);
            else          v = make_float4(acc[i][0].y + q4.x, acc[i][1].y + q4.y,
                                          acc[i][2].y + q4.z, acc[i][3].y + q4.w);
            *(float4*)(out + off) = v;
        }
    }
}

// ---------------------------------------------------------------------------
// Launch. Input order: query, key, value, query_pos, reference_points_cam,
// bev_mask, spatial_shapes, W_value, b_value, W_offsets, b_offsets,
// W_attn, b_attn, W_out, b_out.
// ---------------------------------------------------------------------------
extern "C" void kernel_launch(void* const* d_in, const int* in_sizes, int n_in,
                              void* d_out, int out_size)
{
    const float* query = (const float*)d_in[0];
    // d_in[1] = key: unused by the reference math
    const float* value = (const float*)d_in[2];
    const float* qpos  = (const float*)d_in[3];
    const float* refp  = (const float*)d_in[4];
    const unsigned char* mask = (const unsigned char*)d_in[5];
    // d_in[6] = spatial_shapes (static, hardcoded H=32, W=88)
    const float* Wv   = (const float*)d_in[7];
    const float* bv   = (const float*)d_in[8];
    const float* Woff = (const float*)d_in[9];
    const float* boff = (const float*)d_in[10];
    const float* Wa   = (const float*)d_in[11];
    const float* ba   = (const float*)d_in[12];
    const float* Wo   = (const float*)d_in[13];
    const float* bo   = (const float*)d_in[14];
    float* out = (float*)d_out;

    k_prep  <<<148, 256>>>((const uint4*)mask);
    k_proj  <<<VBLOCKS + QBLOCKS, 256>>>(value, Wv, bv, query, qpos, Woff, boff, Wa, ba);
    k_sample<<<NROWS / 4, 128>>>(refp, mask);
    k_out   <<<OBLOCKS, 256>>>(query, Wo, bo, out);
}